// round 13
// baseline (speedup 1.0000x reference)
#include <cuda_runtime.h>
#include <cuda_bf16.h>
#include <cstdint>

#define BDIM 32
#define HH 14
#define WW 14
#define LL 196
#define DIMC 512
#define EE 4
#define KK 4
#define RR 4
#define MM (BDIM*LL)        // 6272
#define NOUT (EE*2*DIMC)    // 4096
#define MT (MM/128)         // 49
#define NT (NOUT/128)       // 32

// ---- scratch (device globals; no allocs allowed) ----
__device__ float g_xz[(size_t)MM*NOUT];
__device__ float g_xc[(size_t)EE*MM*DIMC];
__device__ float g_P[(size_t)EE*MM*24];
__device__ float g_y4[(size_t)EE*KK*BDIM*LL*DIMC];
__device__ float g_acc[(size_t)MM*DIMC];
__device__ float g_part[BDIM*4*DIMC];
__device__ float g_gr[784*8];
__device__ float g_gate[MM*EE];
__device__ float g_comb[MM*EE];
__device__ __align__(16) __nv_bfloat16 g_Ah[(size_t)MM*DIMC];
__device__ __align__(16) __nv_bfloat16 g_Al[(size_t)MM*DIMC];
__device__ __align__(16) __nv_bfloat16 g_Bh[(size_t)NOUT*DIMC];
__device__ __align__(16) __nv_bfloat16 g_Bl[(size_t)NOUT*DIMC];

__device__ __forceinline__ uint32_t smem_u32(const void* p){
  uint32_t a;
  asm("{ .reg .u64 t; cvta.to.shared.u64 t, %1; cvt.u32.u64 %0, t; }" : "=r"(a) : "l"(p));
  return a;
}
__device__ __forceinline__ void cp16(uint32_t dst, const void* src){
  asm volatile("cp.async.cg.shared.global [%0], [%1], 16;" :: "r"(dst), "l"(src));
}
__device__ __forceinline__ void cp_commit(){ asm volatile("cp.async.commit_group;"); }
__device__ __forceinline__ void cp_wait0(){ asm volatile("cp.async.wait_group 0;"); }
__device__ __forceinline__ void mma_bf16(float* c, const uint32_t* a, const uint32_t* b){
  asm volatile("mma.sync.aligned.m16n8k16.row.col.f32.bf16.bf16.f32 "
    "{%0,%1,%2,%3}, {%4,%5,%6,%7}, {%8,%9}, {%0,%1,%2,%3};"
    : "+f"(c[0]),"+f"(c[1]),"+f"(c[2]),"+f"(c[3])
    : "r"(a[0]),"r"(a[1]),"r"(a[2]),"r"(a[3]), "r"(b[0]),"r"(b[1]));
}
__device__ __forceinline__ void ldsm_x4(uint32_t* r, uint32_t addr){
  asm volatile("ldmatrix.sync.aligned.m8n8.x4.shared.b16 {%0,%1,%2,%3}, [%4];"
    : "=r"(r[0]),"=r"(r[1]),"=r"(r[2]),"=r"(r[3]) : "r"(addr));
}
__device__ __forceinline__ void ldsm_x2(uint32_t* r, uint32_t addr){
  asm volatile("ldmatrix.sync.aligned.m8n8.x2.shared.b16 {%0,%1}, [%2];"
    : "=r"(r[0]),"=r"(r[1]) : "r"(addr));
}
__device__ __forceinline__ float warp_sum(float v){
  #pragma unroll
  for(int o=16;o;o>>=1) v += __shfl_xor_sync(0xffffffffu, v, o);
  return v;
}

// ---------------- bf16 split conversion ----------------
__global__ void convert_kernel(const float* __restrict__ A, const float* __restrict__ Bw){
  size_t u = (size_t)blockIdx.x*blockDim.x + threadIdx.x;
  const float* src; __nv_bfloat16 *dh, *dl;
  size_t nA = (size_t)MM*DIMC/8;
  if(u < nA){ src = A + u*8; dh = g_Ah + u*8; dl = g_Al + u*8; }
  else{
    u -= nA;
    if(u >= (size_t)NOUT*DIMC/8) return;
    src = Bw + u*8; dh = g_Bh + u*8; dl = g_Bl + u*8;
  }
  float4 v0 = *(const float4*)src;
  float4 v1 = *(const float4*)(src+4);
  float v[8] = {v0.x,v0.y,v0.z,v0.w,v1.x,v1.y,v1.z,v1.w};
  __align__(16) __nv_bfloat16 hi[8];
  __align__(16) __nv_bfloat16 lo[8];
  #pragma unroll
  for(int i=0;i<8;i++){
    hi[i]=__float2bfloat16(v[i]);
    lo[i]=__float2bfloat16(v[i]-__bfloat162float(hi[i]));
  }
  *(uint4*)dh = *(uint4*)hi;
  *(uint4*)dl = *(uint4*)lo;
}

// ---------------- split-bf16 HMMA GEMM, N-half selectable (zpart) ----------------
#define RSTR 80
#define TILE_B 10240
#define STAGE_B 40960
__global__ void __launch_bounds__(256,2) gemm_mma_kernel(int zpart){
  extern __shared__ __align__(16) uint8_t smem[];
  uint32_t sb = smem_u32(smem);
  int tid = threadIdx.x;
  int warp = tid>>5, lane = tid&31;
  int wm = warp>>2, wn = warp&3;       // 2 x 4
  int gid = lane>>2, tig = lane&3;
  int g = blockIdx.x, bm = blockIdx.y;
  int bn = (g&3) | (zpart<<2) | ((g>>2)<<3);

  uint32_t ofsA = (uint32_t)((lane&15)*RSTR + (lane>>4)*16);
  uint32_t ofsB = (uint32_t)((lane&7)*RSTR + ((lane>>3)&1)*16);

  float acc[4][4][4];
  #pragma unroll
  for(int i=0;i<4;i++)
    #pragma unroll
    for(int j=0;j<4;j++)
      #pragma unroll
      for(int q=0;q<4;q++) acc[i][j][q]=0.f;

  int lr = (tid>>2), lq = tid&3;
  const __nv_bfloat16* gsrc[4];
  gsrc[0] = g_Ah + (size_t)(bm*128)*DIMC;
  gsrc[1] = g_Al + (size_t)(bm*128)*DIMC;
  gsrc[2] = g_Bh + (size_t)(bn*128)*DIMC;
  gsrc[3] = g_Bl + (size_t)(bn*128)*DIMC;

  auto load_stage = [&](int s, int kt){
    uint32_t base = sb + s*STAGE_B;
    #pragma unroll
    for(int t=0;t<8;t++){
      int tile = t>>1;
      int r = lr + (t&1)*64;
      uint32_t dst = base + tile*TILE_B + r*RSTR + lq*16;
      cp16(dst, gsrc[tile] + (size_t)r*DIMC + kt*32 + lq*8);
    }
    cp_commit();
  };

  load_stage(0, 0);
  const int NK = DIMC/32; // 16
  for(int kt=0; kt<NK; kt++){
    cp_wait0();
    __syncthreads();
    if(kt+1<NK) load_stage((kt+1)&1, kt+1);
    uint32_t stg = sb + (kt&1)*STAGE_B;
    #pragma unroll
    for(int kk=0;kk<2;kk++){
      uint32_t aB = stg + (wm*64)*RSTR + kk*32 + ofsA;
      uint32_t bB = stg + 2*TILE_B + (wn*32)*RSTR + kk*32 + ofsB;
      uint32_t bh[4][2], bl[4][2];
      #pragma unroll
      for(int nt=0;nt<4;nt++){
        ldsm_x2(bh[nt], bB + nt*8*RSTR);
        ldsm_x2(bl[nt], bB + nt*8*RSTR + TILE_B);
      }
      #pragma unroll
      for(int mt=0;mt<4;mt++){
        uint32_t ah[4], al[4];
        ldsm_x4(ah, aB + mt*16*RSTR);
        ldsm_x4(al, aB + mt*16*RSTR + TILE_B);
        #pragma unroll
        for(int nt=0;nt<4;nt++) mma_bf16(acc[mt][nt], ah, bh[nt]);
        #pragma unroll
        for(int nt=0;nt<4;nt++) mma_bf16(acc[mt][nt], ah, bl[nt]);
        #pragma unroll
        for(int nt=0;nt<4;nt++) mma_bf16(acc[mt][nt], al, bh[nt]);
      }
    }
  }
  #pragma unroll
  for(int mt=0;mt<4;mt++){
    int r0 = bm*128 + wm*64 + mt*16 + gid;
    #pragma unroll
    for(int nt=0;nt<4;nt++){
      int c0 = bn*128 + wn*32 + nt*8 + tig*2;
      float2 v0 = {acc[mt][nt][0], acc[mt][nt][1]};
      float2 v1 = {acc[mt][nt][2], acc[mt][nt][3]};
      *(float2*)(g_xz + (size_t)r0*NOUT + c0)     = v0;
      *(float2*)(g_xz + (size_t)(r0+8)*NOUT + c0) = v1;
    }
  }
}

// ---------------- gating + per-block aux partials ----------------
__global__ void gating_kernel(const float* __restrict__ x,
                              const float* __restrict__ q,
                              const float* __restrict__ temp){
  __shared__ float sq[EE*DIMC];
  __shared__ float spart[8][8];
  int tid = threadIdx.x;
  for(int i=tid;i<EE*DIMC;i+=blockDim.x) sq[i]=q[i];
  __syncthreads();
  int wip = tid>>5;
  int warp = blockIdx.x*8 + wip;
  int lane = tid & 31;
  const float* xr = x + (size_t)warp*DIMC;
  float p0=0.f,p1=0.f,p2=0.f,p3=0.f;
  for(int j=lane;j<DIMC;j+=32){
    float xv = xr[j];
    p0 = fmaf(xv, sq[j],        p0);
    p1 = fmaf(xv, sq[DIMC+j],   p1);
    p2 = fmaf(xv, sq[2*DIMC+j], p2);
    p3 = fmaf(xv, sq[3*DIMC+j], p3);
  }
  p0=warp_sum(p0); p1=warp_sum(p1); p2=warp_sum(p2); p3=warp_sum(p3);
  if(lane==0){
    float t = temp[0];
    float lg[4] = {p0/t, p1/t, p2/t, p3/t};
    float mx = fmaxf(fmaxf(lg[0],lg[1]),fmaxf(lg[2],lg[3]));
    float s=0.f, g[4];
    #pragma unroll
    for(int e=0;e<4;e++){ g[e]=expf(lg[e]-mx); s+=g[e]; }
    #pragma unroll
    for(int e=0;e<4;e++){ g[e]/=s; g_gate[warp*4+e]=g[e]; }
    int i0=0;
    #pragma unroll
    for(int e=1;e<4;e++) if(g[e]>g[i0]) i0=e;
    int i1=-1;
    #pragma unroll
    for(int e=0;e<4;e++){ if(e==i0) continue; if(i1<0 || g[e]>g[i1]) i1=e; }
    float ws = g[i0]+g[i1];
    float c[4]={0.f,0.f,0.f,0.f};
    c[i0]=g[i0]/ws; c[i1]=g[i1]/ws;
    #pragma unroll
    for(int e=0;e<4;e++){
      g_comb[warp*4+e]=c[e];
      spart[wip][e]   = g[e];
      spart[wip][4+e] = (c[e]>0.f) ? 0.5f : 0.f;
    }
  }
  __syncthreads();
  if(tid<8){
    float s=0.f;
    #pragma unroll
    for(int w=0;w<8;w++) s += spart[w][tid];
    g_gr[blockIdx.x*8 + tid] = s;
  }
}

__global__ void gr2_kernel(float* d_out, int out_size){
  __shared__ float sh[256];
  int tid=threadIdx.x;
  int r = tid>>3, v = tid&7;
  float s=0.f;
  for(int i=r;i<784;i+=32) s += g_gr[i*8+v];
  sh[tid]=s; __syncthreads();
  for(int st=128; st>=8; st>>=1){ if(tid<st) sh[tid]+=sh[tid+st]; __syncthreads(); }
  if(tid==0){
    float tot=0.f;
    #pragma unroll
    for(int e=0;e<4;e++) tot += (sh[e]/(float)MM)*(sh[4+e]/(float)MM);
    d_out[out_size-1] = 0.01f*(tot*0.25f)*16.f;
  }
}

// ---------------- depthwise 3x3 conv + silu (half plane per thread) ----------------
__global__ void __launch_bounds__(512) conv2_kernel(const float* __restrict__ conv_w,
                                                    const float* __restrict__ conv_b){
  int b = blockIdx.x, e = blockIdx.y, zh = blockIdx.z;
  int d = threadIdx.x;
  const float* wp = conv_w + ((size_t)e*DIMC + d)*9;
  float w00=wp[0],w01=wp[1],w02=wp[2],w10=wp[3],w11=wp[4],w12=wp[5],w20=wp[6],w21=wp[7],w22=wp[8];
  float bias = conv_b[e*DIMC+d];
  const float* in = g_xz + (size_t)(b*LL)*NOUT + e*1024 + d;
  float* outp = g_xc + ((size_t)e*MM + b*LL)*DIMC + d;
  int h0 = zh*7;
  float rm[14], rc[14], rp[14];
  if(h0>0){
    #pragma unroll
    for(int w=0;w<14;w++) rm[w]=in[(size_t)((h0-1)*14+w)*NOUT];
  } else {
    #pragma unroll
    for(int w=0;w<14;w++) rm[w]=0.f;
  }
  #pragma unroll
  for(int w=0;w<14;w++) rc[w]=in[(size_t)(h0*14+w)*NOUT];
  #pragma unroll
  for(int i=0;i<7;i++){
    int h = h0 + i;
    if(h<13){
      #pragma unroll
      for(int w=0;w<14;w++) rp[w]=in[(size_t)((h+1)*14+w)*NOUT];
    } else {
      #pragma unroll
      for(int w=0;w<14;w++) rp[w]=0.f;
    }
    #pragma unroll
    for(int w=0;w<14;w++){
      float acc=bias;
      if(w>0){ acc=fmaf(rm[w-1],w00,acc); acc=fmaf(rc[w-1],w10,acc); acc=fmaf(rp[w-1],w20,acc); }
      acc=fmaf(rm[w],w01,acc); acc=fmaf(rc[w],w11,acc); acc=fmaf(rp[w],w21,acc);
      if(w<13){ acc=fmaf(rm[w+1],w02,acc); acc=fmaf(rc[w+1],w12,acc); acc=fmaf(rp[w+1],w22,acc); }
      outp[(size_t)(h*14+w)*DIMC] = acc/(1.f+__expf(-acc));
    }
    #pragma unroll
    for(int w=0;w<14;w++){ rm[w]=rc[w]; rc[w]=rp[w]; }
  }
}

// ---------------- x_proj: P[e][m][24], warp per row ----------------
__global__ void __launch_bounds__(256) pproj_kernel(const float* __restrict__ x_proj_w){
  int e = blockIdx.y;
  int warp = threadIdx.x>>5, lane = threadIdx.x&31;
  int m = blockIdx.x*8 + warp;
  const float* row = g_xc + ((size_t)e*MM+m)*DIMC;
  float4 xv[4];
  #pragma unroll
  for(int i=0;i<4;i++) xv[i] = *(const float4*)(row + i*128 + lane*4);
  const float* wb = x_proj_w + (size_t)e*24*DIMC;
  #pragma unroll
  for(int c=0;c<24;c++){
    const float* wr = wb + (size_t)c*DIMC;
    float p=0.f;
    #pragma unroll
    for(int i=0;i<4;i++){
      float4 wv = *(const float4*)(wr + i*128 + lane*4);
      p = fmaf(xv[i].x,wv.x, fmaf(xv[i].y,wv.y, fmaf(xv[i].z,wv.z, fmaf(xv[i].w,wv.w, p))));
    }
    p = warp_sum(p);
    if(lane==0) g_P[((size_t)e*MM+m)*24 + c] = p;
  }
}

// ---------------- selective scan (vector sP loads, padded to 8) ----------------
__global__ void __launch_bounds__(512) scan_kernel(const float* __restrict__ dt_proj_w,
                            const float* __restrict__ dt_proj_b,
                            const float* __restrict__ A_logs,
                            const float* __restrict__ Ds){
  int bx = blockIdx.x;
  int b = bx & 31;
  int k = (bx>>5)&3;
  int e = bx>>7;
  int d = threadIdx.x;
  __shared__ __align__(16) float sP[LL*8];
  __shared__ short sidx[LL];
  for(int t=threadIdx.x; t<LL; t+=blockDim.x){
    int tt = (k&1) ? (LL-1-t) : t;
    int idx = (k>=2) ? ((tt%HH)*WW + tt/HH) : tt;
    sidx[t] = (short)idx;
  }
  __syncthreads();
  for(int i=threadIdx.x;i<LL*6;i+=blockDim.x){
    int t=i/6, c=i-t*6;
    sP[t*8+c] = g_P[(((size_t)e*MM + b*LL + sidx[t])*24) + k*6 + c];
  }
  const float* dtw = dt_proj_w + (((size_t)(e*KK+k))*DIMC + d)*RR;
  float w0=dtw[0], w1=dtw[1], w2=dtw[2], w3=dtw[3];
  float dtb = dt_proj_b[(e*KK+k)*DIMC+d];
  float A  = -__expf(A_logs[e*(KK*DIMC) + k*DIMC + d]);
  float Dv = Ds[e*(KK*DIMC) + k*DIMC + d];
  __syncthreads();
  const float* xcb = g_xc + ((size_t)e*MM + b*LL)*DIMC + d;
  float* yb = g_y4 + (((size_t)(e*KK+k)*BDIM + b)*LL)*DIMC + d;
  float h = 0.f;
  for(int t=0;t<LL;t++){
    int idx = sidx[t];
    float xv = xcb[(size_t)idx*DIMC];
    float4 pv = *(const float4*)(sP + t*8);
    float2 pw = *(const float2*)(sP + t*8 + 4);
    float s = fmaf(pv.x,w0, fmaf(pv.y,w1, fmaf(pv.z,w2, fmaf(pv.w,w3, dtb))));
    float dt = (s > 15.f) ? s : __logf(1.f + __expf(s));
    float dA = __expf(dt*A);
    h = fmaf(dA, h, dt*xv*pw.x);
    yb[(size_t)idx*DIMC] = fmaf(h, pw.y, xv*Dv);
  }
}

// ---------------- merge: single-pass (16 loads up front, one barrier) ----------------
__global__ void __launch_bounds__(512) merge_kernel(const float* __restrict__ norm_w,
                             const float* __restrict__ norm_b){
  int m = blockIdx.x;
  int d = threadIdx.x;
  int b = m / LL, l = m % LL;
  __shared__ float sh1[4][16], sh2[4][16];
  int wid = d>>5, lane = d&31;
  float v[4], z[4];
  #pragma unroll
  for(int e=0;e<4;e++){
    float a0 = g_y4[ (((size_t)((e*KK+0)*BDIM + b))*LL + l)*DIMC + d ];
    float a1 = g_y4[ (((size_t)((e*KK+1)*BDIM + b))*LL + l)*DIMC + d ];
    float a2 = g_y4[ (((size_t)((e*KK+2)*BDIM + b))*LL + l)*DIMC + d ];
    float a3 = g_y4[ (((size_t)((e*KK+3)*BDIM + b))*LL + l)*DIMC + d ];
    z[e] = g_xz[(size_t)m*NOUT + e*1024 + DIMC + d];
    v[e] = (a0+a1)+(a2+a3);
  }
  #pragma unroll
  for(int e=0;e<4;e++){
    float s1 = warp_sum(v[e]);
    float s2 = warp_sum(v[e]*v[e]);
    if(lane==0){ sh1[e][wid]=s1; sh2[e][wid]=s2; }
  }
  __syncthreads();
  float accd = 0.f;
  #pragma unroll
  for(int e=0;e<4;e++){
    float t1=0.f, t2=0.f;
    #pragma unroll
    for(int i=0;i<16;i++){ t1+=sh1[e][i]; t2+=sh2[e][i]; }
    float mu  = t1 * (1.f/DIMC);
    float var = t2 * (1.f/DIMC) - mu*mu;
    float nv = (v[e]-mu)*rsqrtf(var+1e-5f)*norm_w[e*DIMC+d] + norm_b[e*DIMC+d];
    float sz = z[e] / (1.f + __expf(-z[e]));
    accd = fmaf(nv*sz, g_comb[m*4+e], accd);
  }
  g_acc[(size_t)m*DIMC + d] = accd;
}

// ---------------- final mean over L (2 phases) ----------------
__global__ void out1_kernel(){
  int b = blockIdx.x, qq = blockIdx.y, d = threadIdx.x;
  float s = 0.f;
  #pragma unroll 7
  for(int l=qq*49; l<qq*49+49; l++) s += g_acc[((size_t)(b*LL+l))*DIMC + d];
  g_part[(b*4+qq)*DIMC + d] = s;
}
__global__ void out2_kernel(float* d_out){
  int b = blockIdx.x, d = threadIdx.x;
  float s = g_part[(b*4+0)*DIMC+d] + g_part[(b*4+1)*DIMC+d]
          + g_part[(b*4+2)*DIMC+d] + g_part[(b*4+3)*DIMC+d];
  d_out[b*DIMC + d] = s * (1.f/(float)LL);
}

extern "C" void kernel_launch(void* const* d_in, const int* in_sizes, int n_in,
                              void* d_out, int out_size){
  const float* x         = (const float*)d_in[0];
  const float* q         = (const float*)d_in[1];
  const float* temp      = (const float*)d_in[2];
  const float* in_proj_w = (const float*)d_in[3];
  const float* conv_w    = (const float*)d_in[4];
  const float* conv_b    = (const float*)d_in[5];
  const float* x_proj_w  = (const float*)d_in[6];
  const float* dt_proj_w = (const float*)d_in[7];
  const float* dt_proj_b = (const float*)d_in[8];
  const float* A_logs    = (const float*)d_in[9];
  const float* Ds        = (const float*)d_in[10];
  const float* norm_w    = (const float*)d_in[11];
  const float* norm_b    = (const float*)d_in[12];
  float* out = (float*)d_out;

  static cudaStream_t s2 = 0;
  static cudaEvent_t ev1 = 0, evx = 0, ev2 = 0;
  if(!s2){
    cudaStreamCreateWithFlags(&s2, cudaStreamNonBlocking);
    cudaEventCreateWithFlags(&ev1, cudaEventDisableTiming);
    cudaEventCreateWithFlags(&evx, cudaEventDisableTiming);
    cudaEventCreateWithFlags(&ev2, cudaEventDisableTiming);
  }

  const int GEMM_SMEM = 2*STAGE_B; // 81920
  cudaFuncSetAttribute(gemm_mma_kernel, cudaFuncAttributeMaxDynamicSharedMemorySize, GEMM_SMEM);

  size_t conv_units = (size_t)(MM + NOUT)*DIMC/8;
  convert_kernel<<<(int)((conv_units+255)/256), 256>>>(x, in_proj_w);

  // fork: s2 runs gating/aux (concurrent with x-GEMM), then z-GEMM AFTER x-GEMM
  cudaEventRecord(ev1, 0);
  cudaStreamWaitEvent(s2, ev1, 0);
  gating_kernel<<<784, 256, 0, s2>>>(x, q, temp);
  gr2_kernel<<<1, 256, 0, s2>>>(out, out_size);

  gemm_mma_kernel<<<dim3(16, MT), 256, GEMM_SMEM>>>(0);   // x-half (main, full chip)
  cudaEventRecord(evx, 0);
  cudaStreamWaitEvent(s2, evx, 0);
  gemm_mma_kernel<<<dim3(16, MT), 256, GEMM_SMEM, s2>>>(1); // z-half overlaps conv chain
  cudaEventRecord(ev2, s2);

  conv2_kernel<<<dim3(BDIM, EE, 2), 512>>>(conv_w, conv_b);
  pproj_kernel<<<dim3(MM/8, EE), 256>>>(x_proj_w);
  scan_kernel<<<EE*KK*BDIM, 512>>>(dt_proj_w, dt_proj_b, A_logs, Ds);

  // join: z-half + gating needed by merge
  cudaStreamWaitEvent(0, ev2, 0);
  merge_kernel<<<MM, 512>>>(norm_w, norm_b);
  out1_kernel<<<dim3(BDIM,4), 512>>>();
  out2_kernel<<<BDIM, 512>>>(out);
}

// round 14
// speedup vs baseline: 1.0150x; 1.0150x over previous
#include <cuda_runtime.h>
#include <cuda_bf16.h>
#include <cstdint>

#define BDIM 32
#define HH 14
#define WW 14
#define LL 196
#define DIMC 512
#define EE 4
#define KK 4
#define RR 4
#define MM (BDIM*LL)        // 6272
#define NOUT (EE*2*DIMC)    // 4096
#define MT (MM/128)         // 49
#define NT (NOUT/128)       // 32

// ---- scratch (device globals; no allocs allowed) ----
__device__ float g_xz[(size_t)MM*NOUT];
__device__ float g_xc[(size_t)EE*MM*DIMC];
__device__ float g_P[(size_t)EE*MM*24];
__device__ float g_y4[(size_t)EE*KK*BDIM*LL*DIMC];
__device__ float g_acc[(size_t)MM*DIMC];
__device__ float g_part[BDIM*4*DIMC];
__device__ float g_gr[784*8];
__device__ float g_gate[MM*EE];
__device__ float g_comb[MM*EE];
__device__ __align__(16) __nv_bfloat16 g_Ah[(size_t)MM*DIMC];
__device__ __align__(16) __nv_bfloat16 g_Al[(size_t)MM*DIMC];
__device__ __align__(16) __nv_bfloat16 g_Bh[(size_t)NOUT*DIMC];
__device__ __align__(16) __nv_bfloat16 g_Bl[(size_t)NOUT*DIMC];

__device__ __forceinline__ uint32_t smem_u32(const void* p){
  uint32_t a;
  asm("{ .reg .u64 t; cvta.to.shared.u64 t, %1; cvt.u32.u64 %0, t; }" : "=r"(a) : "l"(p));
  return a;
}
__device__ __forceinline__ void cp16(uint32_t dst, const void* src){
  asm volatile("cp.async.cg.shared.global [%0], [%1], 16;" :: "r"(dst), "l"(src));
}
__device__ __forceinline__ void cp_commit(){ asm volatile("cp.async.commit_group;"); }
__device__ __forceinline__ void cp_wait0(){ asm volatile("cp.async.wait_group 0;"); }
__device__ __forceinline__ void mma_bf16(float* c, const uint32_t* a, const uint32_t* b){
  asm volatile("mma.sync.aligned.m16n8k16.row.col.f32.bf16.bf16.f32 "
    "{%0,%1,%2,%3}, {%4,%5,%6,%7}, {%8,%9}, {%0,%1,%2,%3};"
    : "+f"(c[0]),"+f"(c[1]),"+f"(c[2]),"+f"(c[3])
    : "r"(a[0]),"r"(a[1]),"r"(a[2]),"r"(a[3]), "r"(b[0]),"r"(b[1]));
}
__device__ __forceinline__ void ldsm_x4(uint32_t* r, uint32_t addr){
  asm volatile("ldmatrix.sync.aligned.m8n8.x4.shared.b16 {%0,%1,%2,%3}, [%4];"
    : "=r"(r[0]),"=r"(r[1]),"=r"(r[2]),"=r"(r[3]) : "r"(addr));
}
__device__ __forceinline__ void ldsm_x2(uint32_t* r, uint32_t addr){
  asm volatile("ldmatrix.sync.aligned.m8n8.x2.shared.b16 {%0,%1}, [%2];"
    : "=r"(r[0]),"=r"(r[1]) : "r"(addr));
}
__device__ __forceinline__ float warp_sum(float v){
  #pragma unroll
  for(int o=16;o;o>>=1) v += __shfl_xor_sync(0xffffffffu, v, o);
  return v;
}

// ---------------- bf16 split conversion ----------------
__global__ void convert_kernel(const float* __restrict__ A, const float* __restrict__ Bw){
  size_t u = (size_t)blockIdx.x*blockDim.x + threadIdx.x;
  const float* src; __nv_bfloat16 *dh, *dl;
  size_t nA = (size_t)MM*DIMC/8;
  if(u < nA){ src = A + u*8; dh = g_Ah + u*8; dl = g_Al + u*8; }
  else{
    u -= nA;
    if(u >= (size_t)NOUT*DIMC/8) return;
    src = Bw + u*8; dh = g_Bh + u*8; dl = g_Bl + u*8;
  }
  float4 v0 = *(const float4*)src;
  float4 v1 = *(const float4*)(src+4);
  float v[8] = {v0.x,v0.y,v0.z,v0.w,v1.x,v1.y,v1.z,v1.w};
  __align__(16) __nv_bfloat16 hi[8];
  __align__(16) __nv_bfloat16 lo[8];
  #pragma unroll
  for(int i=0;i<8;i++){
    hi[i]=__float2bfloat16(v[i]);
    lo[i]=__float2bfloat16(v[i]-__bfloat162float(hi[i]));
  }
  *(uint4*)dh = *(uint4*)hi;
  *(uint4*)dl = *(uint4*)lo;
}

// ---------------- split-bf16 HMMA GEMM (full grid, proven config) ----------------
// BM=128 BN=128 BK=32, 8 warps (2x4), warp tile 64x32, 2-stage, 2 CTA/SM.
#define RSTR 80
#define TILE_B 10240
#define STAGE_B 40960
__global__ void __launch_bounds__(256,2) gemm_mma_kernel(){
  extern __shared__ __align__(16) uint8_t smem[];
  uint32_t sb = smem_u32(smem);
  int tid = threadIdx.x;
  int warp = tid>>5, lane = tid&31;
  int wm = warp>>2, wn = warp&3;       // 2 x 4
  int gid = lane>>2, tig = lane&3;
  int bn = blockIdx.x, bm = blockIdx.y;

  uint32_t ofsA = (uint32_t)((lane&15)*RSTR + (lane>>4)*16);
  uint32_t ofsB = (uint32_t)((lane&7)*RSTR + ((lane>>3)&1)*16);

  float acc[4][4][4];
  #pragma unroll
  for(int i=0;i<4;i++)
    #pragma unroll
    for(int j=0;j<4;j++)
      #pragma unroll
      for(int q=0;q<4;q++) acc[i][j][q]=0.f;

  int lr = (tid>>2), lq = tid&3;
  const __nv_bfloat16* gsrc[4];
  gsrc[0] = g_Ah + (size_t)(bm*128)*DIMC;
  gsrc[1] = g_Al + (size_t)(bm*128)*DIMC;
  gsrc[2] = g_Bh + (size_t)(bn*128)*DIMC;
  gsrc[3] = g_Bl + (size_t)(bn*128)*DIMC;

  auto load_stage = [&](int s, int kt){
    uint32_t base = sb + s*STAGE_B;
    #pragma unroll
    for(int t=0;t<8;t++){
      int tile = t>>1;
      int r = lr + (t&1)*64;
      uint32_t dst = base + tile*TILE_B + r*RSTR + lq*16;
      cp16(dst, gsrc[tile] + (size_t)r*DIMC + kt*32 + lq*8);
    }
    cp_commit();
  };

  load_stage(0, 0);
  const int NK = DIMC/32; // 16
  for(int kt=0; kt<NK; kt++){
    cp_wait0();
    __syncthreads();
    if(kt+1<NK) load_stage((kt+1)&1, kt+1);
    uint32_t stg = sb + (kt&1)*STAGE_B;
    #pragma unroll
    for(int kk=0;kk<2;kk++){
      uint32_t aB = stg + (wm*64)*RSTR + kk*32 + ofsA;
      uint32_t bB = stg + 2*TILE_B + (wn*32)*RSTR + kk*32 + ofsB;
      uint32_t bh[4][2], bl[4][2];
      #pragma unroll
      for(int nt=0;nt<4;nt++){
        ldsm_x2(bh[nt], bB + nt*8*RSTR);
        ldsm_x2(bl[nt], bB + nt*8*RSTR + TILE_B);
      }
      #pragma unroll
      for(int mt=0;mt<4;mt++){
        uint32_t ah[4], al[4];
        ldsm_x4(ah, aB + mt*16*RSTR);
        ldsm_x4(al, aB + mt*16*RSTR + TILE_B);
        #pragma unroll
        for(int nt=0;nt<4;nt++) mma_bf16(acc[mt][nt], ah, bh[nt]);
        #pragma unroll
        for(int nt=0;nt<4;nt++) mma_bf16(acc[mt][nt], ah, bl[nt]);
        #pragma unroll
        for(int nt=0;nt<4;nt++) mma_bf16(acc[mt][nt], al, bh[nt]);
      }
    }
  }
  #pragma unroll
  for(int mt=0;mt<4;mt++){
    int r0 = bm*128 + wm*64 + mt*16 + gid;
    #pragma unroll
    for(int nt=0;nt<4;nt++){
      int c0 = bn*128 + wn*32 + nt*8 + tig*2;
      float2 v0 = {acc[mt][nt][0], acc[mt][nt][1]};
      float2 v1 = {acc[mt][nt][2], acc[mt][nt][3]};
      *(float2*)(g_xz + (size_t)r0*NOUT + c0)     = v0;
      *(float2*)(g_xz + (size_t)(r0+8)*NOUT + c0) = v1;
    }
  }
}

// ---------------- gating + per-block aux partials ----------------
__global__ void gating_kernel(const float* __restrict__ x,
                              const float* __restrict__ q,
                              const float* __restrict__ temp){
  __shared__ float sq[EE*DIMC];
  __shared__ float spart[8][8];
  int tid = threadIdx.x;
  for(int i=tid;i<EE*DIMC;i+=blockDim.x) sq[i]=q[i];
  __syncthreads();
  int wip = tid>>5;
  int warp = blockIdx.x*8 + wip;
  int lane = tid & 31;
  const float* xr = x + (size_t)warp*DIMC;
  float p0=0.f,p1=0.f,p2=0.f,p3=0.f;
  for(int j=lane;j<DIMC;j+=32){
    float xv = xr[j];
    p0 = fmaf(xv, sq[j],        p0);
    p1 = fmaf(xv, sq[DIMC+j],   p1);
    p2 = fmaf(xv, sq[2*DIMC+j], p2);
    p3 = fmaf(xv, sq[3*DIMC+j], p3);
  }
  p0=warp_sum(p0); p1=warp_sum(p1); p2=warp_sum(p2); p3=warp_sum(p3);
  if(lane==0){
    float t = temp[0];
    float lg[4] = {p0/t, p1/t, p2/t, p3/t};
    float mx = fmaxf(fmaxf(lg[0],lg[1]),fmaxf(lg[2],lg[3]));
    float s=0.f, g[4];
    #pragma unroll
    for(int e=0;e<4;e++){ g[e]=expf(lg[e]-mx); s+=g[e]; }
    #pragma unroll
    for(int e=0;e<4;e++){ g[e]/=s; g_gate[warp*4+e]=g[e]; }
    int i0=0;
    #pragma unroll
    for(int e=1;e<4;e++) if(g[e]>g[i0]) i0=e;
    int i1=-1;
    #pragma unroll
    for(int e=0;e<4;e++){ if(e==i0) continue; if(i1<0 || g[e]>g[i1]) i1=e; }
    float ws = g[i0]+g[i1];
    float c[4]={0.f,0.f,0.f,0.f};
    c[i0]=g[i0]/ws; c[i1]=g[i1]/ws;
    #pragma unroll
    for(int e=0;e<4;e++){
      g_comb[warp*4+e]=c[e];
      spart[wip][e]   = g[e];
      spart[wip][4+e] = (c[e]>0.f) ? 0.5f : 0.f;
    }
  }
  __syncthreads();
  if(tid<8){
    float s=0.f;
    #pragma unroll
    for(int w=0;w<8;w++) s += spart[w][tid];
    g_gr[blockIdx.x*8 + tid] = s;
  }
}

__global__ void gr2_kernel(float* d_out, int out_size){
  __shared__ float sh[256];
  int tid=threadIdx.x;
  int r = tid>>3, v = tid&7;
  float s=0.f;
  for(int i=r;i<784;i+=32) s += g_gr[i*8+v];
  sh[tid]=s; __syncthreads();
  for(int st=128; st>=8; st>>=1){ if(tid<st) sh[tid]+=sh[tid+st]; __syncthreads(); }
  if(tid==0){
    float tot=0.f;
    #pragma unroll
    for(int e=0;e<4;e++) tot += (sh[e]/(float)MM)*(sh[4+e]/(float)MM);
    d_out[out_size-1] = 0.01f*(tot*0.25f)*16.f;
  }
}

// ---------------- depthwise 3x3 conv + silu (half plane per thread) ----------------
__global__ void __launch_bounds__(512) conv2_kernel(const float* __restrict__ conv_w,
                                                    const float* __restrict__ conv_b){
  int b = blockIdx.x, e = blockIdx.y, zh = blockIdx.z;
  int d = threadIdx.x;
  const float* wp = conv_w + ((size_t)e*DIMC + d)*9;
  float w00=wp[0],w01=wp[1],w02=wp[2],w10=wp[3],w11=wp[4],w12=wp[5],w20=wp[6],w21=wp[7],w22=wp[8];
  float bias = conv_b[e*DIMC+d];
  const float* in = g_xz + (size_t)(b*LL)*NOUT + e*1024 + d;
  float* outp = g_xc + ((size_t)e*MM + b*LL)*DIMC + d;
  int h0 = zh*7;
  float rm[14], rc[14], rp[14];
  if(h0>0){
    #pragma unroll
    for(int w=0;w<14;w++) rm[w]=in[(size_t)((h0-1)*14+w)*NOUT];
  } else {
    #pragma unroll
    for(int w=0;w<14;w++) rm[w]=0.f;
  }
  #pragma unroll
  for(int w=0;w<14;w++) rc[w]=in[(size_t)(h0*14+w)*NOUT];
  #pragma unroll
  for(int i=0;i<7;i++){
    int h = h0 + i;
    if(h<13){
      #pragma unroll
      for(int w=0;w<14;w++) rp[w]=in[(size_t)((h+1)*14+w)*NOUT];
    } else {
      #pragma unroll
      for(int w=0;w<14;w++) rp[w]=0.f;
    }
    #pragma unroll
    for(int w=0;w<14;w++){
      float acc=bias;
      if(w>0){ acc=fmaf(rm[w-1],w00,acc); acc=fmaf(rc[w-1],w10,acc); acc=fmaf(rp[w-1],w20,acc); }
      acc=fmaf(rm[w],w01,acc); acc=fmaf(rc[w],w11,acc); acc=fmaf(rp[w],w21,acc);
      if(w<13){ acc=fmaf(rm[w+1],w02,acc); acc=fmaf(rc[w+1],w12,acc); acc=fmaf(rp[w+1],w22,acc); }
      outp[(size_t)(h*14+w)*DIMC] = acc/(1.f+__expf(-acc));
    }
    #pragma unroll
    for(int w=0;w<14;w++){ rm[w]=rc[w]; rc[w]=rp[w]; }
  }
}

// ---------------- x_proj: P[e][m][24], warp per row ----------------
__global__ void __launch_bounds__(256) pproj_kernel(const float* __restrict__ x_proj_w){
  int e = blockIdx.y;
  int warp = threadIdx.x>>5, lane = threadIdx.x&31;
  int m = blockIdx.x*8 + warp;
  const float* row = g_xc + ((size_t)e*MM+m)*DIMC;
  float4 xv[4];
  #pragma unroll
  for(int i=0;i<4;i++) xv[i] = *(const float4*)(row + i*128 + lane*4);
  const float* wb = x_proj_w + (size_t)e*24*DIMC;
  #pragma unroll
  for(int c=0;c<24;c++){
    const float* wr = wb + (size_t)c*DIMC;
    float p=0.f;
    #pragma unroll
    for(int i=0;i<4;i++){
      float4 wv = *(const float4*)(wr + i*128 + lane*4);
      p = fmaf(xv[i].x,wv.x, fmaf(xv[i].y,wv.y, fmaf(xv[i].z,wv.z, fmaf(xv[i].w,wv.w, p))));
    }
    p = warp_sum(p);
    if(lane==0) g_P[((size_t)e*MM+m)*24 + c] = p;
  }
}

// ---------------- selective scan (vector sP loads, padded to 8) ----------------
__global__ void __launch_bounds__(512) scan_kernel(const float* __restrict__ dt_proj_w,
                            const float* __restrict__ dt_proj_b,
                            const float* __restrict__ A_logs,
                            const float* __restrict__ Ds){
  int bx = blockIdx.x;
  int b = bx & 31;
  int k = (bx>>5)&3;
  int e = bx>>7;
  int d = threadIdx.x;
  __shared__ __align__(16) float sP[LL*8];
  __shared__ short sidx[LL];
  for(int t=threadIdx.x; t<LL; t+=blockDim.x){
    int tt = (k&1) ? (LL-1-t) : t;
    int idx = (k>=2) ? ((tt%HH)*WW + tt/HH) : tt;
    sidx[t] = (short)idx;
  }
  __syncthreads();
  for(int i=threadIdx.x;i<LL*6;i+=blockDim.x){
    int t=i/6, c=i-t*6;
    sP[t*8+c] = g_P[(((size_t)e*MM + b*LL + sidx[t])*24) + k*6 + c];
  }
  const float* dtw = dt_proj_w + (((size_t)(e*KK+k))*DIMC + d)*RR;
  float w0=dtw[0], w1=dtw[1], w2=dtw[2], w3=dtw[3];
  float dtb = dt_proj_b[(e*KK+k)*DIMC+d];
  float A  = -__expf(A_logs[e*(KK*DIMC) + k*DIMC + d]);
  float Dv = Ds[e*(KK*DIMC) + k*DIMC + d];
  __syncthreads();
  const float* xcb = g_xc + ((size_t)e*MM + b*LL)*DIMC + d;
  float* yb = g_y4 + (((size_t)(e*KK+k)*BDIM + b)*LL)*DIMC + d;
  float h = 0.f;
  for(int t=0;t<LL;t++){
    int idx = sidx[t];
    float xv = xcb[(size_t)idx*DIMC];
    float4 pv = *(const float4*)(sP + t*8);
    float2 pw = *(const float2*)(sP + t*8 + 4);
    float s = fmaf(pv.x,w0, fmaf(pv.y,w1, fmaf(pv.z,w2, fmaf(pv.w,w3, dtb))));
    float dt = (s > 15.f) ? s : __logf(1.f + __expf(s));
    float dA = __expf(dt*A);
    h = fmaf(dA, h, dt*xv*pw.x);
    yb[(size_t)idx*DIMC] = fmaf(h, pw.y, xv*Dv);
  }
}

// ---------------- merge: single-pass (16 loads up front, one barrier) ----------------
__global__ void __launch_bounds__(512) merge_kernel(const float* __restrict__ norm_w,
                             const float* __restrict__ norm_b){
  int m = blockIdx.x;
  int d = threadIdx.x;
  int b = m / LL, l = m % LL;
  __shared__ float sh1[4][16], sh2[4][16];
  int wid = d>>5, lane = d&31;
  float v[4], z[4];
  #pragma unroll
  for(int e=0;e<4;e++){
    float a0 = g_y4[ (((size_t)((e*KK+0)*BDIM + b))*LL + l)*DIMC + d ];
    float a1 = g_y4[ (((size_t)((e*KK+1)*BDIM + b))*LL + l)*DIMC + d ];
    float a2 = g_y4[ (((size_t)((e*KK+2)*BDIM + b))*LL + l)*DIMC + d ];
    float a3 = g_y4[ (((size_t)((e*KK+3)*BDIM + b))*LL + l)*DIMC + d ];
    z[e] = g_xz[(size_t)m*NOUT + e*1024 + DIMC + d];
    v[e] = (a0+a1)+(a2+a3);
  }
  #pragma unroll
  for(int e=0;e<4;e++){
    float s1 = warp_sum(v[e]);
    float s2 = warp_sum(v[e]*v[e]);
    if(lane==0){ sh1[e][wid]=s1; sh2[e][wid]=s2; }
  }
  __syncthreads();
  float accd = 0.f;
  #pragma unroll
  for(int e=0;e<4;e++){
    float t1=0.f, t2=0.f;
    #pragma unroll
    for(int i=0;i<16;i++){ t1+=sh1[e][i]; t2+=sh2[e][i]; }
    float mu  = t1 * (1.f/DIMC);
    float var = t2 * (1.f/DIMC) - mu*mu;
    float nv = (v[e]-mu)*rsqrtf(var+1e-5f)*norm_w[e*DIMC+d] + norm_b[e*DIMC+d];
    float sz = z[e] / (1.f + __expf(-z[e]));
    accd = fmaf(nv*sz, g_comb[m*4+e], accd);
  }
  g_acc[(size_t)m*DIMC + d] = accd;
}

// ---------------- final mean over L (2 phases) ----------------
__global__ void out1_kernel(){
  int b = blockIdx.x, qq = blockIdx.y, d = threadIdx.x;
  float s = 0.f;
  #pragma unroll 7
  for(int l=qq*49; l<qq*49+49; l++) s += g_acc[((size_t)(b*LL+l))*DIMC + d];
  g_part[(b*4+qq)*DIMC + d] = s;
}
__global__ void out2_kernel(float* d_out){
  int b = blockIdx.x, d = threadIdx.x;
  float s = g_part[(b*4+0)*DIMC+d] + g_part[(b*4+1)*DIMC+d]
          + g_part[(b*4+2)*DIMC+d] + g_part[(b*4+3)*DIMC+d];
  d_out[b*DIMC + d] = s * (1.f/(float)LL);
}

extern "C" void kernel_launch(void* const* d_in, const int* in_sizes, int n_in,
                              void* d_out, int out_size){
  const float* x         = (const float*)d_in[0];
  const float* q         = (const float*)d_in[1];
  const float* temp      = (const float*)d_in[2];
  const float* in_proj_w = (const float*)d_in[3];
  const float* conv_w    = (const float*)d_in[4];
  const float* conv_b    = (const float*)d_in[5];
  const float* x_proj_w  = (const float*)d_in[6];
  const float* dt_proj_w = (const float*)d_in[7];
  const float* dt_proj_b = (const float*)d_in[8];
  const float* A_logs    = (const float*)d_in[9];
  const float* Ds        = (const float*)d_in[10];
  const float* norm_w    = (const float*)d_in[11];
  const float* norm_b    = (const float*)d_in[12];
  float* out = (float*)d_out;

  static cudaStream_t s2 = 0;
  static cudaEvent_t ev0 = 0, ev2 = 0;
  if(!s2){
    cudaStreamCreateWithFlags(&s2, cudaStreamNonBlocking);
    cudaEventCreateWithFlags(&ev0, cudaEventDisableTiming);
    cudaEventCreateWithFlags(&ev2, cudaEventDisableTiming);
  }

  const int GEMM_SMEM = 2*STAGE_B; // 81920
  cudaFuncSetAttribute(gemm_mma_kernel, cudaFuncAttributeMaxDynamicSharedMemorySize, GEMM_SMEM);

  // fork immediately: gating/aux depend only on raw inputs; they hide under
  // convert + GEMM on the main stream.
  cudaEventRecord(ev0, 0);
  cudaStreamWaitEvent(s2, ev0, 0);
  gating_kernel<<<784, 256, 0, s2>>>(x, q, temp);
  gr2_kernel<<<1, 256, 0, s2>>>(out, out_size);
  cudaEventRecord(ev2, s2);

  size_t conv_units = (size_t)(MM + NOUT)*DIMC/8;
  convert_kernel<<<(int)((conv_units+255)/256), 256>>>(x, in_proj_w);
  gemm_mma_kernel<<<dim3(NT, MT), 256, GEMM_SMEM>>>();
  conv2_kernel<<<dim3(BDIM, EE, 2), 512>>>(conv_w, conv_b);
  pproj_kernel<<<dim3(MM/8, EE), 256>>>(x_proj_w);
  scan_kernel<<<EE*KK*BDIM, 512>>>(dt_proj_w, dt_proj_b, A_logs, Ds);

  // join: gating results (g_comb) needed by merge
  cudaStreamWaitEvent(0, ev2, 0);
  merge_kernel<<<MM, 512>>>(norm_w, norm_b);
  out1_kernel<<<dim3(BDIM,4), 512>>>();
  out2_kernel<<<BDIM, 512>>>(out);
}

// round 15
// speedup vs baseline: 1.0508x; 1.0353x over previous
#include <cuda_runtime.h>
#include <cuda_bf16.h>
#include <cstdint>

#define BDIM 32
#define HH 14
#define WW 14
#define LL 196
#define DIMC 512
#define EE 4
#define KK 4
#define RR 4
#define MM (BDIM*LL)        // 6272
#define NOUT (EE*2*DIMC)    // 4096
#define MT (MM/128)         // 49
#define NT (NOUT/128)       // 32

// ---- scratch (device globals; no allocs allowed) ----
__device__ float g_xz[(size_t)MM*NOUT];
__device__ float g_xc[(size_t)EE*MM*DIMC];
__device__ float g_P[(size_t)EE*MM*24];
__device__ float g_y4[(size_t)EE*KK*BDIM*LL*DIMC];
__device__ float g_acc[(size_t)MM*DIMC];
__device__ float g_part[BDIM*4*DIMC];
__device__ float g_gr[784*8];
__device__ float g_gate[MM*EE];
__device__ float g_comb[MM*EE];
__device__ __align__(16) __nv_bfloat16 g_Ah[(size_t)MM*DIMC];
__device__ __align__(16) __nv_bfloat16 g_Al[(size_t)MM*DIMC];
__device__ __align__(16) __nv_bfloat16 g_Bh[(size_t)NOUT*DIMC];
__device__ __align__(16) __nv_bfloat16 g_Bl[(size_t)NOUT*DIMC];

__device__ __forceinline__ uint32_t smem_u32(const void* p){
  uint32_t a;
  asm("{ .reg .u64 t; cvta.to.shared.u64 t, %1; cvt.u32.u64 %0, t; }" : "=r"(a) : "l"(p));
  return a;
}
__device__ __forceinline__ void cp16(uint32_t dst, const void* src){
  asm volatile("cp.async.cg.shared.global [%0], [%1], 16;" :: "r"(dst), "l"(src));
}
__device__ __forceinline__ void cp_commit(){ asm volatile("cp.async.commit_group;"); }
__device__ __forceinline__ void cp_wait0(){ asm volatile("cp.async.wait_group 0;"); }
__device__ __forceinline__ void mma_bf16(float* c, const uint32_t* a, const uint32_t* b){
  asm volatile("mma.sync.aligned.m16n8k16.row.col.f32.bf16.bf16.f32 "
    "{%0,%1,%2,%3}, {%4,%5,%6,%7}, {%8,%9}, {%0,%1,%2,%3};"
    : "+f"(c[0]),"+f"(c[1]),"+f"(c[2]),"+f"(c[3])
    : "r"(a[0]),"r"(a[1]),"r"(a[2]),"r"(a[3]), "r"(b[0]),"r"(b[1]));
}
__device__ __forceinline__ void ldsm_x4(uint32_t* r, uint32_t addr){
  asm volatile("ldmatrix.sync.aligned.m8n8.x4.shared.b16 {%0,%1,%2,%3}, [%4];"
    : "=r"(r[0]),"=r"(r[1]),"=r"(r[2]),"=r"(r[3]) : "r"(addr));
}
__device__ __forceinline__ void ldsm_x2(uint32_t* r, uint32_t addr){
  asm volatile("ldmatrix.sync.aligned.m8n8.x2.shared.b16 {%0,%1}, [%2];"
    : "=r"(r[0]),"=r"(r[1]) : "r"(addr));
}
__device__ __forceinline__ float warp_sum(float v){
  #pragma unroll
  for(int o=16;o;o>>=1) v += __shfl_xor_sync(0xffffffffu, v, o);
  return v;
}

// ---------------- bf16 split conversion ----------------
__global__ void convert_kernel(const float* __restrict__ A, const float* __restrict__ Bw){
  size_t u = (size_t)blockIdx.x*blockDim.x + threadIdx.x;
  const float* src; __nv_bfloat16 *dh, *dl;
  size_t nA = (size_t)MM*DIMC/8;
  if(u < nA){ src = A + u*8; dh = g_Ah + u*8; dl = g_Al + u*8; }
  else{
    u -= nA;
    if(u >= (size_t)NOUT*DIMC/8) return;
    src = Bw + u*8; dh = g_Bh + u*8; dl = g_Bl + u*8;
  }
  float4 v0 = *(const float4*)src;
  float4 v1 = *(const float4*)(src+4);
  float v[8] = {v0.x,v0.y,v0.z,v0.w,v1.x,v1.y,v1.z,v1.w};
  __align__(16) __nv_bfloat16 hi[8];
  __align__(16) __nv_bfloat16 lo[8];
  #pragma unroll
  for(int i=0;i<8;i++){
    hi[i]=__float2bfloat16(v[i]);
    lo[i]=__float2bfloat16(v[i]-__bfloat162float(hi[i]));
  }
  *(uint4*)dh = *(uint4*)hi;
  *(uint4*)dl = *(uint4*)lo;
}

// ---------------- split-bf16 HMMA GEMM, N-half selectable (zpart) ----------------
#define RSTR 80
#define TILE_B 10240
#define STAGE_B 40960
__global__ void __launch_bounds__(256,2) gemm_mma_kernel(int zpart){
  extern __shared__ __align__(16) uint8_t smem[];
  uint32_t sb = smem_u32(smem);
  int tid = threadIdx.x;
  int warp = tid>>5, lane = tid&31;
  int wm = warp>>2, wn = warp&3;       // 2 x 4
  int gid = lane>>2, tig = lane&3;
  int g = blockIdx.x, bm = blockIdx.y;
  int bn = (g&3) | (zpart<<2) | ((g>>2)<<3);

  uint32_t ofsA = (uint32_t)((lane&15)*RSTR + (lane>>4)*16);
  uint32_t ofsB = (uint32_t)((lane&7)*RSTR + ((lane>>3)&1)*16);

  float acc[4][4][4];
  #pragma unroll
  for(int i=0;i<4;i++)
    #pragma unroll
    for(int j=0;j<4;j++)
      #pragma unroll
      for(int q=0;q<4;q++) acc[i][j][q]=0.f;

  int lr = (tid>>2), lq = tid&3;
  const __nv_bfloat16* gsrc[4];
  gsrc[0] = g_Ah + (size_t)(bm*128)*DIMC;
  gsrc[1] = g_Al + (size_t)(bm*128)*DIMC;
  gsrc[2] = g_Bh + (size_t)(bn*128)*DIMC;
  gsrc[3] = g_Bl + (size_t)(bn*128)*DIMC;

  auto load_stage = [&](int s, int kt){
    uint32_t base = sb + s*STAGE_B;
    #pragma unroll
    for(int t=0;t<8;t++){
      int tile = t>>1;
      int r = lr + (t&1)*64;
      uint32_t dst = base + tile*TILE_B + r*RSTR + lq*16;
      cp16(dst, gsrc[tile] + (size_t)r*DIMC + kt*32 + lq*8);
    }
    cp_commit();
  };

  load_stage(0, 0);
  const int NK = DIMC/32; // 16
  for(int kt=0; kt<NK; kt++){
    cp_wait0();
    __syncthreads();
    if(kt+1<NK) load_stage((kt+1)&1, kt+1);
    uint32_t stg = sb + (kt&1)*STAGE_B;
    #pragma unroll
    for(int kk=0;kk<2;kk++){
      uint32_t aB = stg + (wm*64)*RSTR + kk*32 + ofsA;
      uint32_t bB = stg + 2*TILE_B + (wn*32)*RSTR + kk*32 + ofsB;
      uint32_t bh[4][2], bl[4][2];
      #pragma unroll
      for(int nt=0;nt<4;nt++){
        ldsm_x2(bh[nt], bB + nt*8*RSTR);
        ldsm_x2(bl[nt], bB + nt*8*RSTR + TILE_B);
      }
      #pragma unroll
      for(int mt=0;mt<4;mt++){
        uint32_t ah[4], al[4];
        ldsm_x4(ah, aB + mt*16*RSTR);
        ldsm_x4(al, aB + mt*16*RSTR + TILE_B);
        #pragma unroll
        for(int nt=0;nt<4;nt++) mma_bf16(acc[mt][nt], ah, bh[nt]);
        #pragma unroll
        for(int nt=0;nt<4;nt++) mma_bf16(acc[mt][nt], ah, bl[nt]);
        #pragma unroll
        for(int nt=0;nt<4;nt++) mma_bf16(acc[mt][nt], al, bh[nt]);
      }
    }
  }
  #pragma unroll
  for(int mt=0;mt<4;mt++){
    int r0 = bm*128 + wm*64 + mt*16 + gid;
    #pragma unroll
    for(int nt=0;nt<4;nt++){
      int c0 = bn*128 + wn*32 + nt*8 + tig*2;
      float2 v0 = {acc[mt][nt][0], acc[mt][nt][1]};
      float2 v1 = {acc[mt][nt][2], acc[mt][nt][3]};
      *(float2*)(g_xz + (size_t)r0*NOUT + c0)     = v0;
      *(float2*)(g_xz + (size_t)(r0+8)*NOUT + c0) = v1;
    }
  }
}

// ---------------- gating + per-block aux partials ----------------
__global__ void gating_kernel(const float* __restrict__ x,
                              const float* __restrict__ q,
                              const float* __restrict__ temp){
  __shared__ float sq[EE*DIMC];
  __shared__ float spart[8][8];
  int tid = threadIdx.x;
  for(int i=tid;i<EE*DIMC;i+=blockDim.x) sq[i]=q[i];
  __syncthreads();
  int wip = tid>>5;
  int warp = blockIdx.x*8 + wip;
  int lane = tid & 31;
  const float* xr = x + (size_t)warp*DIMC;
  float p0=0.f,p1=0.f,p2=0.f,p3=0.f;
  for(int j=lane;j<DIMC;j+=32){
    float xv = xr[j];
    p0 = fmaf(xv, sq[j],        p0);
    p1 = fmaf(xv, sq[DIMC+j],   p1);
    p2 = fmaf(xv, sq[2*DIMC+j], p2);
    p3 = fmaf(xv, sq[3*DIMC+j], p3);
  }
  p0=warp_sum(p0); p1=warp_sum(p1); p2=warp_sum(p2); p3=warp_sum(p3);
  if(lane==0){
    float t = temp[0];
    float lg[4] = {p0/t, p1/t, p2/t, p3/t};
    float mx = fmaxf(fmaxf(lg[0],lg[1]),fmaxf(lg[2],lg[3]));
    float s=0.f, g[4];
    #pragma unroll
    for(int e=0;e<4;e++){ g[e]=expf(lg[e]-mx); s+=g[e]; }
    #pragma unroll
    for(int e=0;e<4;e++){ g[e]/=s; g_gate[warp*4+e]=g[e]; }
    int i0=0;
    #pragma unroll
    for(int e=1;e<4;e++) if(g[e]>g[i0]) i0=e;
    int i1=-1;
    #pragma unroll
    for(int e=0;e<4;e++){ if(e==i0) continue; if(i1<0 || g[e]>g[i1]) i1=e; }
    float ws = g[i0]+g[i1];
    float c[4]={0.f,0.f,0.f,0.f};
    c[i0]=g[i0]/ws; c[i1]=g[i1]/ws;
    #pragma unroll
    for(int e=0;e<4;e++){
      g_comb[warp*4+e]=c[e];
      spart[wip][e]   = g[e];
      spart[wip][4+e] = (c[e]>0.f) ? 0.5f : 0.f;
    }
  }
  __syncthreads();
  if(tid<8){
    float s=0.f;
    #pragma unroll
    for(int w=0;w<8;w++) s += spart[w][tid];
    g_gr[blockIdx.x*8 + tid] = s;
  }
}

__global__ void gr2_kernel(float* d_out, int out_size){
  __shared__ float sh[256];
  int tid=threadIdx.x;
  int r = tid>>3, v = tid&7;
  float s=0.f;
  for(int i=r;i<784;i+=32) s += g_gr[i*8+v];
  sh[tid]=s; __syncthreads();
  for(int st=128; st>=8; st>>=1){ if(tid<st) sh[tid]+=sh[tid+st]; __syncthreads(); }
  if(tid==0){
    float tot=0.f;
    #pragma unroll
    for(int e=0;e<4;e++) tot += (sh[e]/(float)MM)*(sh[4+e]/(float)MM);
    d_out[out_size-1] = 0.01f*(tot*0.25f)*16.f;
  }
}

// ---------------- depthwise 3x3 conv + silu (half plane per thread) ----------------
__global__ void __launch_bounds__(512) conv2_kernel(const float* __restrict__ conv_w,
                                                    const float* __restrict__ conv_b){
  int b = blockIdx.x, e = blockIdx.y, zh = blockIdx.z;
  int d = threadIdx.x;
  const float* wp = conv_w + ((size_t)e*DIMC + d)*9;
  float w00=wp[0],w01=wp[1],w02=wp[2],w10=wp[3],w11=wp[4],w12=wp[5],w20=wp[6],w21=wp[7],w22=wp[8];
  float bias = conv_b[e*DIMC+d];
  const float* in = g_xz + (size_t)(b*LL)*NOUT + e*1024 + d;
  float* outp = g_xc + ((size_t)e*MM + b*LL)*DIMC + d;
  int h0 = zh*7;
  float rm[14], rc[14], rp[14];
  if(h0>0){
    #pragma unroll
    for(int w=0;w<14;w++) rm[w]=in[(size_t)((h0-1)*14+w)*NOUT];
  } else {
    #pragma unroll
    for(int w=0;w<14;w++) rm[w]=0.f;
  }
  #pragma unroll
  for(int w=0;w<14;w++) rc[w]=in[(size_t)(h0*14+w)*NOUT];
  #pragma unroll
  for(int i=0;i<7;i++){
    int h = h0 + i;
    if(h<13){
      #pragma unroll
      for(int w=0;w<14;w++) rp[w]=in[(size_t)((h+1)*14+w)*NOUT];
    } else {
      #pragma unroll
      for(int w=0;w<14;w++) rp[w]=0.f;
    }
    #pragma unroll
    for(int w=0;w<14;w++){
      float acc=bias;
      if(w>0){ acc=fmaf(rm[w-1],w00,acc); acc=fmaf(rc[w-1],w10,acc); acc=fmaf(rp[w-1],w20,acc); }
      acc=fmaf(rm[w],w01,acc); acc=fmaf(rc[w],w11,acc); acc=fmaf(rp[w],w21,acc);
      if(w<13){ acc=fmaf(rm[w+1],w02,acc); acc=fmaf(rc[w+1],w12,acc); acc=fmaf(rp[w+1],w22,acc); }
      outp[(size_t)(h*14+w)*DIMC] = acc/(1.f+__expf(-acc));
    }
    #pragma unroll
    for(int w=0;w<14;w++){ rm[w]=rc[w]; rc[w]=rp[w]; }
  }
}

// ---------------- x_proj: P[e][m][24], warp per row ----------------
__global__ void __launch_bounds__(256) pproj_kernel(const float* __restrict__ x_proj_w){
  int e = blockIdx.y;
  int warp = threadIdx.x>>5, lane = threadIdx.x&31;
  int m = blockIdx.x*8 + warp;
  const float* row = g_xc + ((size_t)e*MM+m)*DIMC;
  float4 xv[4];
  #pragma unroll
  for(int i=0;i<4;i++) xv[i] = *(const float4*)(row + i*128 + lane*4);
  const float* wb = x_proj_w + (size_t)e*24*DIMC;
  #pragma unroll
  for(int c=0;c<24;c++){
    const float* wr = wb + (size_t)c*DIMC;
    float p=0.f;
    #pragma unroll
    for(int i=0;i<4;i++){
      float4 wv = *(const float4*)(wr + i*128 + lane*4);
      p = fmaf(xv[i].x,wv.x, fmaf(xv[i].y,wv.y, fmaf(xv[i].z,wv.z, fmaf(xv[i].w,wv.w, p))));
    }
    p = warp_sum(p);
    if(lane==0) g_P[((size_t)e*MM+m)*24 + c] = p;
  }
}

// ---------------- selective scan (vector sP loads, padded to 8) ----------------
__global__ void __launch_bounds__(512) scan_kernel(const float* __restrict__ dt_proj_w,
                            const float* __restrict__ dt_proj_b,
                            const float* __restrict__ A_logs,
                            const float* __restrict__ Ds){
  int bx = blockIdx.x;
  int b = bx & 31;
  int k = (bx>>5)&3;
  int e = bx>>7;
  int d = threadIdx.x;
  __shared__ __align__(16) float sP[LL*8];
  __shared__ short sidx[LL];
  for(int t=threadIdx.x; t<LL; t+=blockDim.x){
    int tt = (k&1) ? (LL-1-t) : t;
    int idx = (k>=2) ? ((tt%HH)*WW + tt/HH) : tt;
    sidx[t] = (short)idx;
  }
  __syncthreads();
  for(int i=threadIdx.x;i<LL*6;i+=blockDim.x){
    int t=i/6, c=i-t*6;
    sP[t*8+c] = g_P[(((size_t)e*MM + b*LL + sidx[t])*24) + k*6 + c];
  }
  const float* dtw = dt_proj_w + (((size_t)(e*KK+k))*DIMC + d)*RR;
  float w0=dtw[0], w1=dtw[1], w2=dtw[2], w3=dtw[3];
  float dtb = dt_proj_b[(e*KK+k)*DIMC+d];
  float A  = -__expf(A_logs[e*(KK*DIMC) + k*DIMC + d]);
  float Dv = Ds[e*(KK*DIMC) + k*DIMC + d];
  __syncthreads();
  const float* xcb = g_xc + ((size_t)e*MM + b*LL)*DIMC + d;
  float* yb = g_y4 + (((size_t)(e*KK+k)*BDIM + b)*LL)*DIMC + d;
  float h = 0.f;
  for(int t=0;t<LL;t++){
    int idx = sidx[t];
    float xv = xcb[(size_t)idx*DIMC];
    float4 pv = *(const float4*)(sP + t*8);
    float2 pw = *(const float2*)(sP + t*8 + 4);
    float s = fmaf(pv.x,w0, fmaf(pv.y,w1, fmaf(pv.z,w2, fmaf(pv.w,w3, dtb))));
    float dt = (s > 15.f) ? s : __logf(1.f + __expf(s));
    float dA = __expf(dt*A);
    h = fmaf(dA, h, dt*xv*pw.x);
    yb[(size_t)idx*DIMC] = fmaf(h, pw.y, xv*Dv);
  }
}

// ---------------- merge: single-pass (16 loads up front, one barrier) ----------------
__global__ void __launch_bounds__(512) merge_kernel(const float* __restrict__ norm_w,
                             const float* __restrict__ norm_b){
  int m = blockIdx.x;
  int d = threadIdx.x;
  int b = m / LL, l = m % LL;
  __shared__ float sh1[4][16], sh2[4][16];
  int wid = d>>5, lane = d&31;
  float v[4], z[4];
  #pragma unroll
  for(int e=0;e<4;e++){
    float a0 = g_y4[ (((size_t)((e*KK+0)*BDIM + b))*LL + l)*DIMC + d ];
    float a1 = g_y4[ (((size_t)((e*KK+1)*BDIM + b))*LL + l)*DIMC + d ];
    float a2 = g_y4[ (((size_t)((e*KK+2)*BDIM + b))*LL + l)*DIMC + d ];
    float a3 = g_y4[ (((size_t)((e*KK+3)*BDIM + b))*LL + l)*DIMC + d ];
    z[e] = g_xz[(size_t)m*NOUT + e*1024 + DIMC + d];
    v[e] = (a0+a1)+(a2+a3);
  }
  #pragma unroll
  for(int e=0;e<4;e++){
    float s1 = warp_sum(v[e]);
    float s2 = warp_sum(v[e]*v[e]);
    if(lane==0){ sh1[e][wid]=s1; sh2[e][wid]=s2; }
  }
  __syncthreads();
  float accd = 0.f;
  #pragma unroll
  for(int e=0;e<4;e++){
    float t1=0.f, t2=0.f;
    #pragma unroll
    for(int i=0;i<16;i++){ t1+=sh1[e][i]; t2+=sh2[e][i]; }
    float mu  = t1 * (1.f/DIMC);
    float var = t2 * (1.f/DIMC) - mu*mu;
    float nv = (v[e]-mu)*rsqrtf(var+1e-5f)*norm_w[e*DIMC+d] + norm_b[e*DIMC+d];
    float sz = z[e] / (1.f + __expf(-z[e]));
    accd = fmaf(nv*sz, g_comb[m*4+e], accd);
  }
  g_acc[(size_t)m*DIMC + d] = accd;
}

// ---------------- final mean over L (2 phases) ----------------
__global__ void out1_kernel(){
  int b = blockIdx.x, qq = blockIdx.y, d = threadIdx.x;
  float s = 0.f;
  #pragma unroll 7
  for(int l=qq*49; l<qq*49+49; l++) s += g_acc[((size_t)(b*LL+l))*DIMC + d];
  g_part[(b*4+qq)*DIMC + d] = s;
}
__global__ void out2_kernel(float* d_out){
  int b = blockIdx.x, d = threadIdx.x;
  float s = g_part[(b*4+0)*DIMC+d] + g_part[(b*4+1)*DIMC+d]
          + g_part[(b*4+2)*DIMC+d] + g_part[(b*4+3)*DIMC+d];
  d_out[b*DIMC + d] = s * (1.f/(float)LL);
}

extern "C" void kernel_launch(void* const* d_in, const int* in_sizes, int n_in,
                              void* d_out, int out_size){
  const float* x         = (const float*)d_in[0];
  const float* q         = (const float*)d_in[1];
  const float* temp      = (const float*)d_in[2];
  const float* in_proj_w = (const float*)d_in[3];
  const float* conv_w    = (const float*)d_in[4];
  const float* conv_b    = (const float*)d_in[5];
  const float* x_proj_w  = (const float*)d_in[6];
  const float* dt_proj_w = (const float*)d_in[7];
  const float* dt_proj_b = (const float*)d_in[8];
  const float* A_logs    = (const float*)d_in[9];
  const float* Ds        = (const float*)d_in[10];
  const float* norm_w    = (const float*)d_in[11];
  const float* norm_b    = (const float*)d_in[12];
  float* out = (float*)d_out;

  static cudaStream_t s2 = 0;
  static cudaEvent_t ev1 = 0, ev2 = 0;
  if(!s2){
    cudaStreamCreateWithFlags(&s2, cudaStreamNonBlocking);
    cudaEventCreateWithFlags(&ev1, cudaEventDisableTiming);
    cudaEventCreateWithFlags(&ev2, cudaEventDisableTiming);
  }

  const int GEMM_SMEM = 2*STAGE_B; // 81920
  cudaFuncSetAttribute(gemm_mma_kernel, cudaFuncAttributeMaxDynamicSharedMemorySize, GEMM_SMEM);

  size_t conv_units = (size_t)(MM + NOUT)*DIMC/8;
  convert_kernel<<<(int)((conv_units+255)/256), 256>>>(x, in_proj_w);

  // fork (R12 schedule): s2 runs gating/aux + z-half GEMM concurrent with x-half GEMM
  cudaEventRecord(ev1, 0);
  cudaStreamWaitEvent(s2, ev1, 0);

  gemm_mma_kernel<<<dim3(16, MT), 256, GEMM_SMEM>>>(0);          // x-half (main)
  gating_kernel<<<784, 256, 0, s2>>>(x, q, temp);
  gr2_kernel<<<1, 256, 0, s2>>>(out, out_size);
  gemm_mma_kernel<<<dim3(16, MT), 256, GEMM_SMEM, s2>>>(1);      // z-half (s2, concurrent)
  cudaEventRecord(ev2, s2);

  conv2_kernel<<<dim3(BDIM, EE, 2), 512>>>(conv_w, conv_b);
  pproj_kernel<<<dim3(MM/8, EE), 256>>>(x_proj_w);
  scan_kernel<<<EE*KK*BDIM, 512>>>(dt_proj_w, dt_proj_b, A_logs, Ds);

  // join: z-half + gating results needed by merge
  cudaStreamWaitEvent(0, ev2, 0);
  merge_kernel<<<MM, 512>>>(norm_w, norm_b);
  out1_kernel<<<dim3(BDIM,4), 512>>>();
  out2_kernel<<<BDIM, 512>>>(out);
}

// round 16
// speedup vs baseline: 1.0580x; 1.0069x over previous
#include <cuda_runtime.h>
#include <cuda_bf16.h>
#include <cstdint>

#define BDIM 32
#define HH 14
#define WW 14
#define LL 196
#define DIMC 512
#define EE 4
#define KK 4
#define RR 4
#define MM (BDIM*LL)        // 6272
#define NOUT (EE*2*DIMC)    // 4096
#define MT (MM/128)         // 49
#define NT (NOUT/128)       // 32

// ---- scratch (device globals; no allocs allowed) ----
__device__ float g_xz[(size_t)MM*NOUT];
__device__ float g_xc[(size_t)EE*MM*DIMC];
__device__ float g_P[(size_t)EE*MM*24];
__device__ float g_y4[(size_t)EE*KK*BDIM*LL*DIMC];
__device__ float g_acc[(size_t)MM*DIMC];
__device__ float g_part[BDIM*4*DIMC];
__device__ float g_gr[784*8];
__device__ float g_gate[MM*EE];
__device__ float g_comb[MM*EE];
__device__ __align__(16) __nv_bfloat16 g_Ah[(size_t)MM*DIMC];
__device__ __align__(16) __nv_bfloat16 g_Al[(size_t)MM*DIMC];
__device__ __align__(16) __nv_bfloat16 g_Bh[(size_t)NOUT*DIMC];
__device__ __align__(16) __nv_bfloat16 g_Bl[(size_t)NOUT*DIMC];

__device__ __forceinline__ uint32_t smem_u32(const void* p){
  uint32_t a;
  asm("{ .reg .u64 t; cvta.to.shared.u64 t, %1; cvt.u32.u64 %0, t; }" : "=r"(a) : "l"(p));
  return a;
}
__device__ __forceinline__ void cp16(uint32_t dst, const void* src){
  asm volatile("cp.async.cg.shared.global [%0], [%1], 16;" :: "r"(dst), "l"(src));
}
__device__ __forceinline__ void cp_commit(){ asm volatile("cp.async.commit_group;"); }
__device__ __forceinline__ void cp_wait0(){ asm volatile("cp.async.wait_group 0;"); }
__device__ __forceinline__ void mma_bf16(float* c, const uint32_t* a, const uint32_t* b){
  asm volatile("mma.sync.aligned.m16n8k16.row.col.f32.bf16.bf16.f32 "
    "{%0,%1,%2,%3}, {%4,%5,%6,%7}, {%8,%9}, {%0,%1,%2,%3};"
    : "+f"(c[0]),"+f"(c[1]),"+f"(c[2]),"+f"(c[3])
    : "r"(a[0]),"r"(a[1]),"r"(a[2]),"r"(a[3]), "r"(b[0]),"r"(b[1]));
}
__device__ __forceinline__ void ldsm_x4(uint32_t* r, uint32_t addr){
  asm volatile("ldmatrix.sync.aligned.m8n8.x4.shared.b16 {%0,%1,%2,%3}, [%4];"
    : "=r"(r[0]),"=r"(r[1]),"=r"(r[2]),"=r"(r[3]) : "r"(addr));
}
__device__ __forceinline__ void ldsm_x2(uint32_t* r, uint32_t addr){
  asm volatile("ldmatrix.sync.aligned.m8n8.x2.shared.b16 {%0,%1}, [%2];"
    : "=r"(r[0]),"=r"(r[1]) : "r"(addr));
}
__device__ __forceinline__ float warp_sum(float v){
  #pragma unroll
  for(int o=16;o;o>>=1) v += __shfl_xor_sync(0xffffffffu, v, o);
  return v;
}

// ---------------- bf16 split conversion ----------------
__global__ void convert_kernel(const float* __restrict__ A, const float* __restrict__ Bw){
  size_t u = (size_t)blockIdx.x*blockDim.x + threadIdx.x;
  const float* src; __nv_bfloat16 *dh, *dl;
  size_t nA = (size_t)MM*DIMC/8;
  if(u < nA){ src = A + u*8; dh = g_Ah + u*8; dl = g_Al + u*8; }
  else{
    u -= nA;
    if(u >= (size_t)NOUT*DIMC/8) return;
    src = Bw + u*8; dh = g_Bh + u*8; dl = g_Bl + u*8;
  }
  float4 v0 = *(const float4*)src;
  float4 v1 = *(const float4*)(src+4);
  float v[8] = {v0.x,v0.y,v0.z,v0.w,v1.x,v1.y,v1.z,v1.w};
  __align__(16) __nv_bfloat16 hi[8];
  __align__(16) __nv_bfloat16 lo[8];
  #pragma unroll
  for(int i=0;i<8;i++){
    hi[i]=__float2bfloat16(v[i]);
    lo[i]=__float2bfloat16(v[i]-__bfloat162float(hi[i]));
  }
  *(uint4*)dh = *(uint4*)hi;
  *(uint4*)dl = *(uint4*)lo;
}

// ---------------- split-bf16 HMMA GEMM, N-half selectable (zpart) ----------------
#define RSTR 80
#define TILE_B 10240
#define STAGE_B 40960
__global__ void __launch_bounds__(256,2) gemm_mma_kernel(int zpart){
  extern __shared__ __align__(16) uint8_t smem[];
  uint32_t sb = smem_u32(smem);
  int tid = threadIdx.x;
  int warp = tid>>5, lane = tid&31;
  int wm = warp>>2, wn = warp&3;       // 2 x 4
  int gid = lane>>2, tig = lane&3;
  int g = blockIdx.x, bm = blockIdx.y;
  int bn = (g&3) | (zpart<<2) | ((g>>2)<<3);

  uint32_t ofsA = (uint32_t)((lane&15)*RSTR + (lane>>4)*16);
  uint32_t ofsB = (uint32_t)((lane&7)*RSTR + ((lane>>3)&1)*16);

  float acc[4][4][4];
  #pragma unroll
  for(int i=0;i<4;i++)
    #pragma unroll
    for(int j=0;j<4;j++)
      #pragma unroll
      for(int q=0;q<4;q++) acc[i][j][q]=0.f;

  int lr = (tid>>2), lq = tid&3;
  const __nv_bfloat16* gsrc[4];
  gsrc[0] = g_Ah + (size_t)(bm*128)*DIMC;
  gsrc[1] = g_Al + (size_t)(bm*128)*DIMC;
  gsrc[2] = g_Bh + (size_t)(bn*128)*DIMC;
  gsrc[3] = g_Bl + (size_t)(bn*128)*DIMC;

  auto load_stage = [&](int s, int kt){
    uint32_t base = sb + s*STAGE_B;
    #pragma unroll
    for(int t=0;t<8;t++){
      int tile = t>>1;
      int r = lr + (t&1)*64;
      uint32_t dst = base + tile*TILE_B + r*RSTR + lq*16;
      cp16(dst, gsrc[tile] + (size_t)r*DIMC + kt*32 + lq*8);
    }
    cp_commit();
  };

  load_stage(0, 0);
  const int NK = DIMC/32; // 16
  for(int kt=0; kt<NK; kt++){
    cp_wait0();
    __syncthreads();
    if(kt+1<NK) load_stage((kt+1)&1, kt+1);
    uint32_t stg = sb + (kt&1)*STAGE_B;
    #pragma unroll
    for(int kk=0;kk<2;kk++){
      uint32_t aB = stg + (wm*64)*RSTR + kk*32 + ofsA;
      uint32_t bB = stg + 2*TILE_B + (wn*32)*RSTR + kk*32 + ofsB;
      uint32_t bh[4][2], bl[4][2];
      #pragma unroll
      for(int nt=0;nt<4;nt++){
        ldsm_x2(bh[nt], bB + nt*8*RSTR);
        ldsm_x2(bl[nt], bB + nt*8*RSTR + TILE_B);
      }
      #pragma unroll
      for(int mt=0;mt<4;mt++){
        uint32_t ah[4], al[4];
        ldsm_x4(ah, aB + mt*16*RSTR);
        ldsm_x4(al, aB + mt*16*RSTR + TILE_B);
        #pragma unroll
        for(int nt=0;nt<4;nt++) mma_bf16(acc[mt][nt], ah, bh[nt]);
        #pragma unroll
        for(int nt=0;nt<4;nt++) mma_bf16(acc[mt][nt], ah, bl[nt]);
        #pragma unroll
        for(int nt=0;nt<4;nt++) mma_bf16(acc[mt][nt], al, bh[nt]);
      }
    }
  }
  #pragma unroll
  for(int mt=0;mt<4;mt++){
    int r0 = bm*128 + wm*64 + mt*16 + gid;
    #pragma unroll
    for(int nt=0;nt<4;nt++){
      int c0 = bn*128 + wn*32 + nt*8 + tig*2;
      float2 v0 = {acc[mt][nt][0], acc[mt][nt][1]};
      float2 v1 = {acc[mt][nt][2], acc[mt][nt][3]};
      *(float2*)(g_xz + (size_t)r0*NOUT + c0)     = v0;
      *(float2*)(g_xz + (size_t)(r0+8)*NOUT + c0) = v1;
    }
  }
}

// ---------------- gating + per-block aux partials ----------------
__global__ void gating_kernel(const float* __restrict__ x,
                              const float* __restrict__ q,
                              const float* __restrict__ temp){
  __shared__ float sq[EE*DIMC];
  __shared__ float spart[8][8];
  int tid = threadIdx.x;
  for(int i=tid;i<EE*DIMC;i+=blockDim.x) sq[i]=q[i];
  __syncthreads();
  int wip = tid>>5;
  int warp = blockIdx.x*8 + wip;
  int lane = tid & 31;
  const float* xr = x + (size_t)warp*DIMC;
  float p0=0.f,p1=0.f,p2=0.f,p3=0.f;
  for(int j=lane;j<DIMC;j+=32){
    float xv = xr[j];
    p0 = fmaf(xv, sq[j],        p0);
    p1 = fmaf(xv, sq[DIMC+j],   p1);
    p2 = fmaf(xv, sq[2*DIMC+j], p2);
    p3 = fmaf(xv, sq[3*DIMC+j], p3);
  }
  p0=warp_sum(p0); p1=warp_sum(p1); p2=warp_sum(p2); p3=warp_sum(p3);
  if(lane==0){
    float t = temp[0];
    float lg[4] = {p0/t, p1/t, p2/t, p3/t};
    float mx = fmaxf(fmaxf(lg[0],lg[1]),fmaxf(lg[2],lg[3]));
    float s=0.f, g[4];
    #pragma unroll
    for(int e=0;e<4;e++){ g[e]=expf(lg[e]-mx); s+=g[e]; }
    #pragma unroll
    for(int e=0;e<4;e++){ g[e]/=s; g_gate[warp*4+e]=g[e]; }
    int i0=0;
    #pragma unroll
    for(int e=1;e<4;e++) if(g[e]>g[i0]) i0=e;
    int i1=-1;
    #pragma unroll
    for(int e=0;e<4;e++){ if(e==i0) continue; if(i1<0 || g[e]>g[i1]) i1=e; }
    float ws = g[i0]+g[i1];
    float c[4]={0.f,0.f,0.f,0.f};
    c[i0]=g[i0]/ws; c[i1]=g[i1]/ws;
    #pragma unroll
    for(int e=0;e<4;e++){
      g_comb[warp*4+e]=c[e];
      spart[wip][e]   = g[e];
      spart[wip][4+e] = (c[e]>0.f) ? 0.5f : 0.f;
    }
  }
  __syncthreads();
  if(tid<8){
    float s=0.f;
    #pragma unroll
    for(int w=0;w<8;w++) s += spart[w][tid];
    g_gr[blockIdx.x*8 + tid] = s;
  }
}

__global__ void gr2_kernel(float* d_out, int out_size){
  __shared__ float sh[256];
  int tid=threadIdx.x;
  int r = tid>>3, v = tid&7;
  float s=0.f;
  for(int i=r;i<784;i+=32) s += g_gr[i*8+v];
  sh[tid]=s; __syncthreads();
  for(int st=128; st>=8; st>>=1){ if(tid<st) sh[tid]+=sh[tid+st]; __syncthreads(); }
  if(tid==0){
    float tot=0.f;
    #pragma unroll
    for(int e=0;e<4;e++) tot += (sh[e]/(float)MM)*(sh[4+e]/(float)MM);
    d_out[out_size-1] = 0.01f*(tot*0.25f)*16.f;
  }
}

// ---------------- depthwise 3x3 conv + silu (half plane per thread) ----------------
__global__ void __launch_bounds__(512) conv2_kernel(const float* __restrict__ conv_w,
                                                    const float* __restrict__ conv_b){
  int b = blockIdx.x, e = blockIdx.y, zh = blockIdx.z;
  int d = threadIdx.x;
  const float* wp = conv_w + ((size_t)e*DIMC + d)*9;
  float w00=wp[0],w01=wp[1],w02=wp[2],w10=wp[3],w11=wp[4],w12=wp[5],w20=wp[6],w21=wp[7],w22=wp[8];
  float bias = conv_b[e*DIMC+d];
  const float* in = g_xz + (size_t)(b*LL)*NOUT + e*1024 + d;
  float* outp = g_xc + ((size_t)e*MM + b*LL)*DIMC + d;
  int h0 = zh*7;
  float rm[14], rc[14], rp[14];
  if(h0>0){
    #pragma unroll
    for(int w=0;w<14;w++) rm[w]=in[(size_t)((h0-1)*14+w)*NOUT];
  } else {
    #pragma unroll
    for(int w=0;w<14;w++) rm[w]=0.f;
  }
  #pragma unroll
  for(int w=0;w<14;w++) rc[w]=in[(size_t)(h0*14+w)*NOUT];
  #pragma unroll
  for(int i=0;i<7;i++){
    int h = h0 + i;
    if(h<13){
      #pragma unroll
      for(int w=0;w<14;w++) rp[w]=in[(size_t)((h+1)*14+w)*NOUT];
    } else {
      #pragma unroll
      for(int w=0;w<14;w++) rp[w]=0.f;
    }
    #pragma unroll
    for(int w=0;w<14;w++){
      float acc=bias;
      if(w>0){ acc=fmaf(rm[w-1],w00,acc); acc=fmaf(rc[w-1],w10,acc); acc=fmaf(rp[w-1],w20,acc); }
      acc=fmaf(rm[w],w01,acc); acc=fmaf(rc[w],w11,acc); acc=fmaf(rp[w],w21,acc);
      if(w<13){ acc=fmaf(rm[w+1],w02,acc); acc=fmaf(rc[w+1],w12,acc); acc=fmaf(rp[w+1],w22,acc); }
      outp[(size_t)(h*14+w)*DIMC] = acc/(1.f+__expf(-acc));
    }
    #pragma unroll
    for(int w=0;w<14;w++){ rm[w]=rc[w]; rc[w]=rp[w]; }
  }
}

// ---------------- x_proj: P[e][m][24], warp per row ----------------
__global__ void __launch_bounds__(256) pproj_kernel(const float* __restrict__ x_proj_w){
  int e = blockIdx.y;
  int warp = threadIdx.x>>5, lane = threadIdx.x&31;
  int m = blockIdx.x*8 + warp;
  const float* row = g_xc + ((size_t)e*MM+m)*DIMC;
  float4 xv[4];
  #pragma unroll
  for(int i=0;i<4;i++) xv[i] = *(const float4*)(row + i*128 + lane*4);
  const float* wb = x_proj_w + (size_t)e*24*DIMC;
  #pragma unroll
  for(int c=0;c<24;c++){
    const float* wr = wb + (size_t)c*DIMC;
    float p=0.f;
    #pragma unroll
    for(int i=0;i<4;i++){
      float4 wv = *(const float4*)(wr + i*128 + lane*4);
      p = fmaf(xv[i].x,wv.x, fmaf(xv[i].y,wv.y, fmaf(xv[i].z,wv.z, fmaf(xv[i].w,wv.w, p))));
    }
    p = warp_sum(p);
    if(lane==0) g_P[((size_t)e*MM+m)*24 + c] = p;
  }
}

// ---------------- selective scan (evict-first y4 stores, xv prefetch) ----------------
__global__ void __launch_bounds__(512) scan_kernel(const float* __restrict__ dt_proj_w,
                            const float* __restrict__ dt_proj_b,
                            const float* __restrict__ A_logs,
                            const float* __restrict__ Ds){
  int bx = blockIdx.x;
  int b = bx & 31;
  int k = (bx>>5)&3;
  int e = bx>>7;
  int d = threadIdx.x;
  __shared__ __align__(16) float sP[LL*8];
  __shared__ short sidx[LL];
  for(int t=threadIdx.x; t<LL; t+=blockDim.x){
    int tt = (k&1) ? (LL-1-t) : t;
    int idx = (k>=2) ? ((tt%HH)*WW + tt/HH) : tt;
    sidx[t] = (short)idx;
  }
  __syncthreads();
  for(int i=threadIdx.x;i<LL*6;i+=blockDim.x){
    int t=i/6, c=i-t*6;
    sP[t*8+c] = g_P[(((size_t)e*MM + b*LL + sidx[t])*24) + k*6 + c];
  }
  const float* dtw = dt_proj_w + (((size_t)(e*KK+k))*DIMC + d)*RR;
  float w0=dtw[0], w1=dtw[1], w2=dtw[2], w3=dtw[3];
  float dtb = dt_proj_b[(e*KK+k)*DIMC+d];
  float A  = -__expf(A_logs[e*(KK*DIMC) + k*DIMC + d]);
  float Dv = Ds[e*(KK*DIMC) + k*DIMC + d];
  __syncthreads();
  const float* xcb = g_xc + ((size_t)e*MM + b*LL)*DIMC + d;
  float* yb = g_y4 + (((size_t)(e*KK+k)*BDIM + b)*LL)*DIMC + d;
  float h = 0.f;
  int idx_n = sidx[0];
  float xv_n = xcb[(size_t)idx_n*DIMC];
  for(int t=0;t<LL;t++){
    int idx = idx_n;
    float xv = xv_n;
    if(t+1<LL){
      idx_n = sidx[t+1];
      xv_n  = xcb[(size_t)idx_n*DIMC];   // prefetch next step's input
    }
    float4 pv = *(const float4*)(sP + t*8);
    float2 pw = *(const float2*)(sP + t*8 + 4);
    float s = fmaf(pv.x,w0, fmaf(pv.y,w1, fmaf(pv.z,w2, fmaf(pv.w,w3, dtb))));
    float dt = (s > 15.f) ? s : __logf(1.f + __expf(s));
    float dA = __expf(dt*A);
    h = fmaf(dA, h, dt*xv*pw.x);
    __stcs(yb + (size_t)idx*DIMC, fmaf(h, pw.y, xv*Dv));  // evict-first: protect xc in L2
  }
}

// ---------------- merge: single-pass (streaming y4 reads, one barrier) ----------------
__global__ void __launch_bounds__(512) merge_kernel(const float* __restrict__ norm_w,
                             const float* __restrict__ norm_b){
  int m = blockIdx.x;
  int d = threadIdx.x;
  int b = m / LL, l = m % LL;
  __shared__ float sh1[4][16], sh2[4][16];
  int wid = d>>5, lane = d&31;
  float v[4], z[4];
  #pragma unroll
  for(int e=0;e<4;e++){
    float a0 = __ldcs(&g_y4[ (((size_t)((e*KK+0)*BDIM + b))*LL + l)*DIMC + d ]);
    float a1 = __ldcs(&g_y4[ (((size_t)((e*KK+1)*BDIM + b))*LL + l)*DIMC + d ]);
    float a2 = __ldcs(&g_y4[ (((size_t)((e*KK+2)*BDIM + b))*LL + l)*DIMC + d ]);
    float a3 = __ldcs(&g_y4[ (((size_t)((e*KK+3)*BDIM + b))*LL + l)*DIMC + d ]);
    z[e] = g_xz[(size_t)m*NOUT + e*1024 + DIMC + d];
    v[e] = (a0+a1)+(a2+a3);
  }
  #pragma unroll
  for(int e=0;e<4;e++){
    float s1 = warp_sum(v[e]);
    float s2 = warp_sum(v[e]*v[e]);
    if(lane==0){ sh1[e][wid]=s1; sh2[e][wid]=s2; }
  }
  __syncthreads();
  float accd = 0.f;
  #pragma unroll
  for(int e=0;e<4;e++){
    float t1=0.f, t2=0.f;
    #pragma unroll
    for(int i=0;i<16;i++){ t1+=sh1[e][i]; t2+=sh2[e][i]; }
    float mu  = t1 * (1.f/DIMC);
    float var = t2 * (1.f/DIMC) - mu*mu;
    float nv = (v[e]-mu)*rsqrtf(var+1e-5f)*norm_w[e*DIMC+d] + norm_b[e*DIMC+d];
    float sz = z[e] / (1.f + __expf(-z[e]));
    accd = fmaf(nv*sz, g_comb[m*4+e], accd);
  }
  g_acc[(size_t)m*DIMC + d] = accd;
}

// ---------------- final mean over L (2 phases) ----------------
__global__ void out1_kernel(){
  int b = blockIdx.x, qq = blockIdx.y, d = threadIdx.x;
  float s = 0.f;
  #pragma unroll 7
  for(int l=qq*49; l<qq*49+49; l++) s += g_acc[((size_t)(b*LL+l))*DIMC + d];
  g_part[(b*4+qq)*DIMC + d] = s;
}
__global__ void out2_kernel(float* d_out){
  int b = blockIdx.x, d = threadIdx.x;
  float s = g_part[(b*4+0)*DIMC+d] + g_part[(b*4+1)*DIMC+d]
          + g_part[(b*4+2)*DIMC+d] + g_part[(b*4+3)*DIMC+d];
  d_out[b*DIMC + d] = s * (1.f/(float)LL);
}

extern "C" void kernel_launch(void* const* d_in, const int* in_sizes, int n_in,
                              void* d_out, int out_size){
  const float* x         = (const float*)d_in[0];
  const float* q         = (const float*)d_in[1];
  const float* temp      = (const float*)d_in[2];
  const float* in_proj_w = (const float*)d_in[3];
  const float* conv_w    = (const float*)d_in[4];
  const float* conv_b    = (const float*)d_in[5];
  const float* x_proj_w  = (const float*)d_in[6];
  const float* dt_proj_w = (const float*)d_in[7];
  const float* dt_proj_b = (const float*)d_in[8];
  const float* A_logs    = (const float*)d_in[9];
  const float* Ds        = (const float*)d_in[10];
  const float* norm_w    = (const float*)d_in[11];
  const float* norm_b    = (const float*)d_in[12];
  float* out = (float*)d_out;

  static cudaStream_t s2 = 0;
  static cudaEvent_t ev1 = 0, ev2 = 0;
  if(!s2){
    cudaStreamCreateWithFlags(&s2, cudaStreamNonBlocking);
    cudaEventCreateWithFlags(&ev1, cudaEventDisableTiming);
    cudaEventCreateWithFlags(&ev2, cudaEventDisableTiming);
  }

  const int GEMM_SMEM = 2*STAGE_B; // 81920
  cudaFuncSetAttribute(gemm_mma_kernel, cudaFuncAttributeMaxDynamicSharedMemorySize, GEMM_SMEM);

  size_t conv_units = (size_t)(MM + NOUT)*DIMC/8;
  convert_kernel<<<(int)((conv_units+255)/256), 256>>>(x, in_proj_w);

  // fork (R12/R15 schedule): s2 runs gating/aux + z-half GEMM concurrent with x-half GEMM
  cudaEventRecord(ev1, 0);
  cudaStreamWaitEvent(s2, ev1, 0);

  gemm_mma_kernel<<<dim3(16, MT), 256, GEMM_SMEM>>>(0);          // x-half (main)
  gating_kernel<<<784, 256, 0, s2>>>(x, q, temp);
  gr2_kernel<<<1, 256, 0, s2>>>(out, out_size);
  gemm_mma_kernel<<<dim3(16, MT), 256, GEMM_SMEM, s2>>>(1);      // z-half (s2, concurrent)
  cudaEventRecord(ev2, s2);

  conv2_kernel<<<dim3(BDIM, EE, 2), 512>>>(conv_w, conv_b);
  pproj_kernel<<<dim3(MM/8, EE), 256>>>(x_proj_w);
  scan_kernel<<<EE*KK*BDIM, 512>>>(dt_proj_w, dt_proj_b, A_logs, Ds);

  // join: z-half + gating results needed by merge
  cudaStreamWaitEvent(0, ev2, 0);
  merge_kernel<<<MM, 512>>>(norm_w, norm_b);
  out1_kernel<<<dim3(BDIM,4), 512>>>();
  out2_kernel<<<BDIM, 512>>>(out);
}

// round 17
// speedup vs baseline: 1.0845x; 1.0250x over previous
#include <cuda_runtime.h>
#include <cuda_bf16.h>
#include <cstdint>

#define BDIM 32
#define HH 14
#define WW 14
#define LL 196
#define DIMC 512
#define EE 4
#define KK 4
#define RR 4
#define MM (BDIM*LL)        // 6272
#define NOUT (EE*2*DIMC)    // 4096
#define MT (MM/128)         // 49
#define NT (NOUT/128)       // 32

// ---- scratch (device globals; no allocs allowed) ----
__device__ float g_xz[(size_t)MM*NOUT];
__device__ float g_xc[(size_t)EE*MM*DIMC];
__device__ float g_P[(size_t)EE*MM*24];
__device__ float g_y4[(size_t)EE*KK*BDIM*LL*DIMC];
__device__ float g_acc[(size_t)MM*DIMC];
__device__ float g_part[BDIM*4*DIMC];
__device__ float g_gr[784*8];
__device__ float g_gate[MM*EE];
__device__ float g_comb[MM*EE];
__device__ __align__(16) __nv_bfloat16 g_Ah[(size_t)MM*DIMC];
__device__ __align__(16) __nv_bfloat16 g_Al[(size_t)MM*DIMC];
__device__ __align__(16) __nv_bfloat16 g_Bh[(size_t)NOUT*DIMC];
__device__ __align__(16) __nv_bfloat16 g_Bl[(size_t)NOUT*DIMC];

__device__ __forceinline__ uint32_t smem_u32(const void* p){
  uint32_t a;
  asm("{ .reg .u64 t; cvta.to.shared.u64 t, %1; cvt.u32.u64 %0, t; }" : "=r"(a) : "l"(p));
  return a;
}
__device__ __forceinline__ void cp16(uint32_t dst, const void* src){
  asm volatile("cp.async.cg.shared.global [%0], [%1], 16;" :: "r"(dst), "l"(src));
}
__device__ __forceinline__ void cp_commit(){ asm volatile("cp.async.commit_group;"); }
__device__ __forceinline__ void cp_wait0(){ asm volatile("cp.async.wait_group 0;"); }
__device__ __forceinline__ void mma_bf16(float* c, const uint32_t* a, const uint32_t* b){
  asm volatile("mma.sync.aligned.m16n8k16.row.col.f32.bf16.bf16.f32 "
    "{%0,%1,%2,%3}, {%4,%5,%6,%7}, {%8,%9}, {%0,%1,%2,%3};"
    : "+f"(c[0]),"+f"(c[1]),"+f"(c[2]),"+f"(c[3])
    : "r"(a[0]),"r"(a[1]),"r"(a[2]),"r"(a[3]), "r"(b[0]),"r"(b[1]));
}
__device__ __forceinline__ void ldsm_x4(uint32_t* r, uint32_t addr){
  asm volatile("ldmatrix.sync.aligned.m8n8.x4.shared.b16 {%0,%1,%2,%3}, [%4];"
    : "=r"(r[0]),"=r"(r[1]),"=r"(r[2]),"=r"(r[3]) : "r"(addr));
}
__device__ __forceinline__ void ldsm_x2(uint32_t* r, uint32_t addr){
  asm volatile("ldmatrix.sync.aligned.m8n8.x2.shared.b16 {%0,%1}, [%2];"
    : "=r"(r[0]),"=r"(r[1]) : "r"(addr));
}
__device__ __forceinline__ float warp_sum(float v){
  #pragma unroll
  for(int o=16;o;o>>=1) v += __shfl_xor_sync(0xffffffffu, v, o);
  return v;
}

// ---------------- bf16 split conversion ----------------
__global__ void convert_kernel(const float* __restrict__ A, const float* __restrict__ Bw){
  size_t u = (size_t)blockIdx.x*blockDim.x + threadIdx.x;
  const float* src; __nv_bfloat16 *dh, *dl;
  size_t nA = (size_t)MM*DIMC/8;
  if(u < nA){ src = A + u*8; dh = g_Ah + u*8; dl = g_Al + u*8; }
  else{
    u -= nA;
    if(u >= (size_t)NOUT*DIMC/8) return;
    src = Bw + u*8; dh = g_Bh + u*8; dl = g_Bl + u*8;
  }
  float4 v0 = *(const float4*)src;
  float4 v1 = *(const float4*)(src+4);
  float v[8] = {v0.x,v0.y,v0.z,v0.w,v1.x,v1.y,v1.z,v1.w};
  __align__(16) __nv_bfloat16 hi[8];
  __align__(16) __nv_bfloat16 lo[8];
  #pragma unroll
  for(int i=0;i<8;i++){
    hi[i]=__float2bfloat16(v[i]);
    lo[i]=__float2bfloat16(v[i]-__bfloat162float(hi[i]));
  }
  *(uint4*)dh = *(uint4*)hi;
  *(uint4*)dl = *(uint4*)lo;
}

// ---------------- split-bf16 HMMA GEMM, N-half selectable (zpart) ----------------
#define RSTR 80
#define TILE_B 10240
#define STAGE_B 40960
__global__ void __launch_bounds__(256,2) gemm_mma_kernel(int zpart){
  extern __shared__ __align__(16) uint8_t smem[];
  uint32_t sb = smem_u32(smem);
  int tid = threadIdx.x;
  int warp = tid>>5, lane = tid&31;
  int wm = warp>>2, wn = warp&3;       // 2 x 4
  int gid = lane>>2, tig = lane&3;
  int g = blockIdx.x, bm = blockIdx.y;
  int bn = (g&3) | (zpart<<2) | ((g>>2)<<3);

  uint32_t ofsA = (uint32_t)((lane&15)*RSTR + (lane>>4)*16);
  uint32_t ofsB = (uint32_t)((lane&7)*RSTR + ((lane>>3)&1)*16);

  float acc[4][4][4];
  #pragma unroll
  for(int i=0;i<4;i++)
    #pragma unroll
    for(int j=0;j<4;j++)
      #pragma unroll
      for(int q=0;q<4;q++) acc[i][j][q]=0.f;

  int lr = (tid>>2), lq = tid&3;
  const __nv_bfloat16* gsrc[4];
  gsrc[0] = g_Ah + (size_t)(bm*128)*DIMC;
  gsrc[1] = g_Al + (size_t)(bm*128)*DIMC;
  gsrc[2] = g_Bh + (size_t)(bn*128)*DIMC;
  gsrc[3] = g_Bl + (size_t)(bn*128)*DIMC;

  auto load_stage = [&](int s, int kt){
    uint32_t base = sb + s*STAGE_B;
    #pragma unroll
    for(int t=0;t<8;t++){
      int tile = t>>1;
      int r = lr + (t&1)*64;
      uint32_t dst = base + tile*TILE_B + r*RSTR + lq*16;
      cp16(dst, gsrc[tile] + (size_t)r*DIMC + kt*32 + lq*8);
    }
    cp_commit();
  };

  load_stage(0, 0);
  const int NK = DIMC/32; // 16
  for(int kt=0; kt<NK; kt++){
    cp_wait0();
    __syncthreads();
    if(kt+1<NK) load_stage((kt+1)&1, kt+1);
    uint32_t stg = sb + (kt&1)*STAGE_B;
    #pragma unroll
    for(int kk=0;kk<2;kk++){
      uint32_t aB = stg + (wm*64)*RSTR + kk*32 + ofsA;
      uint32_t bB = stg + 2*TILE_B + (wn*32)*RSTR + kk*32 + ofsB;
      uint32_t bh[4][2], bl[4][2];
      #pragma unroll
      for(int nt=0;nt<4;nt++){
        ldsm_x2(bh[nt], bB + nt*8*RSTR);
        ldsm_x2(bl[nt], bB + nt*8*RSTR + TILE_B);
      }
      #pragma unroll
      for(int mt=0;mt<4;mt++){
        uint32_t ah[4], al[4];
        ldsm_x4(ah, aB + mt*16*RSTR);
        ldsm_x4(al, aB + mt*16*RSTR + TILE_B);
        #pragma unroll
        for(int nt=0;nt<4;nt++) mma_bf16(acc[mt][nt], ah, bh[nt]);
        #pragma unroll
        for(int nt=0;nt<4;nt++) mma_bf16(acc[mt][nt], ah, bl[nt]);
        #pragma unroll
        for(int nt=0;nt<4;nt++) mma_bf16(acc[mt][nt], al, bh[nt]);
      }
    }
  }
  #pragma unroll
  for(int mt=0;mt<4;mt++){
    int r0 = bm*128 + wm*64 + mt*16 + gid;
    #pragma unroll
    for(int nt=0;nt<4;nt++){
      int c0 = bn*128 + wn*32 + nt*8 + tig*2;
      float2 v0 = {acc[mt][nt][0], acc[mt][nt][1]};
      float2 v1 = {acc[mt][nt][2], acc[mt][nt][3]};
      *(float2*)(g_xz + (size_t)r0*NOUT + c0)     = v0;
      *(float2*)(g_xz + (size_t)(r0+8)*NOUT + c0) = v1;
    }
  }
}

// ---------------- gating + per-block aux partials ----------------
__global__ void gating_kernel(const float* __restrict__ x,
                              const float* __restrict__ q,
                              const float* __restrict__ temp){
  __shared__ float sq[EE*DIMC];
  __shared__ float spart[8][8];
  int tid = threadIdx.x;
  for(int i=tid;i<EE*DIMC;i+=blockDim.x) sq[i]=q[i];
  __syncthreads();
  int wip = tid>>5;
  int warp = blockIdx.x*8 + wip;
  int lane = tid & 31;
  const float* xr = x + (size_t)warp*DIMC;
  float p0=0.f,p1=0.f,p2=0.f,p3=0.f;
  for(int j=lane;j<DIMC;j+=32){
    float xv = xr[j];
    p0 = fmaf(xv, sq[j],        p0);
    p1 = fmaf(xv, sq[DIMC+j],   p1);
    p2 = fmaf(xv, sq[2*DIMC+j], p2);
    p3 = fmaf(xv, sq[3*DIMC+j], p3);
  }
  p0=warp_sum(p0); p1=warp_sum(p1); p2=warp_sum(p2); p3=warp_sum(p3);
  if(lane==0){
    float t = temp[0];
    float lg[4] = {p0/t, p1/t, p2/t, p3/t};
    float mx = fmaxf(fmaxf(lg[0],lg[1]),fmaxf(lg[2],lg[3]));
    float s=0.f, g[4];
    #pragma unroll
    for(int e=0;e<4;e++){ g[e]=expf(lg[e]-mx); s+=g[e]; }
    #pragma unroll
    for(int e=0;e<4;e++){ g[e]/=s; g_gate[warp*4+e]=g[e]; }
    int i0=0;
    #pragma unroll
    for(int e=1;e<4;e++) if(g[e]>g[i0]) i0=e;
    int i1=-1;
    #pragma unroll
    for(int e=0;e<4;e++){ if(e==i0) continue; if(i1<0 || g[e]>g[i1]) i1=e; }
    float ws = g[i0]+g[i1];
    float c[4]={0.f,0.f,0.f,0.f};
    c[i0]=g[i0]/ws; c[i1]=g[i1]/ws;
    #pragma unroll
    for(int e=0;e<4;e++){
      g_comb[warp*4+e]=c[e];
      spart[wip][e]   = g[e];
      spart[wip][4+e] = (c[e]>0.f) ? 0.5f : 0.f;
    }
  }
  __syncthreads();
  if(tid<8){
    float s=0.f;
    #pragma unroll
    for(int w=0;w<8;w++) s += spart[w][tid];
    g_gr[blockIdx.x*8 + tid] = s;
  }
}

__global__ void gr2_kernel(float* d_out, int out_size){
  __shared__ float sh[256];
  int tid=threadIdx.x;
  int r = tid>>3, v = tid&7;
  float s=0.f;
  for(int i=r;i<784;i+=32) s += g_gr[i*8+v];
  sh[tid]=s; __syncthreads();
  for(int st=128; st>=8; st>>=1){ if(tid<st) sh[tid]+=sh[tid+st]; __syncthreads(); }
  if(tid==0){
    float tot=0.f;
    #pragma unroll
    for(int e=0;e<4;e++) tot += (sh[e]/(float)MM)*(sh[4+e]/(float)MM);
    d_out[out_size-1] = 0.01f*(tot*0.25f)*16.f;
  }
}

// ---------------- depthwise 3x3 conv + silu (half plane per thread) ----------------
__global__ void __launch_bounds__(512) conv2_kernel(const float* __restrict__ conv_w,
                                                    const float* __restrict__ conv_b){
  int b = blockIdx.x, e = blockIdx.y, zh = blockIdx.z;
  int d = threadIdx.x;
  const float* wp = conv_w + ((size_t)e*DIMC + d)*9;
  float w00=wp[0],w01=wp[1],w02=wp[2],w10=wp[3],w11=wp[4],w12=wp[5],w20=wp[6],w21=wp[7],w22=wp[8];
  float bias = conv_b[e*DIMC+d];
  const float* in = g_xz + (size_t)(b*LL)*NOUT + e*1024 + d;
  float* outp = g_xc + ((size_t)e*MM + b*LL)*DIMC + d;
  int h0 = zh*7;
  float rm[14], rc[14], rp[14];
  if(h0>0){
    #pragma unroll
    for(int w=0;w<14;w++) rm[w]=__ldcs(in + (size_t)((h0-1)*14+w)*NOUT);
  } else {
    #pragma unroll
    for(int w=0;w<14;w++) rm[w]=0.f;
  }
  #pragma unroll
  for(int w=0;w<14;w++) rc[w]=__ldcs(in + (size_t)(h0*14+w)*NOUT);
  #pragma unroll
  for(int i=0;i<7;i++){
    int h = h0 + i;
    if(h<13){
      #pragma unroll
      for(int w=0;w<14;w++) rp[w]=__ldcs(in + (size_t)((h+1)*14+w)*NOUT);
    } else {
      #pragma unroll
      for(int w=0;w<14;w++) rp[w]=0.f;
    }
    #pragma unroll
    for(int w=0;w<14;w++){
      float acc=bias;
      if(w>0){ acc=fmaf(rm[w-1],w00,acc); acc=fmaf(rc[w-1],w10,acc); acc=fmaf(rp[w-1],w20,acc); }
      acc=fmaf(rm[w],w01,acc); acc=fmaf(rc[w],w11,acc); acc=fmaf(rp[w],w21,acc);
      if(w<13){ acc=fmaf(rm[w+1],w02,acc); acc=fmaf(rc[w+1],w12,acc); acc=fmaf(rp[w+1],w22,acc); }
      outp[(size_t)(h*14+w)*DIMC] = acc/(1.f+__expf(-acc));
    }
    #pragma unroll
    for(int w=0;w<14;w++){ rm[w]=rc[w]; rc[w]=rp[w]; }
  }
}

// ---------------- x_proj: P[e][m][24], warp per row ----------------
__global__ void __launch_bounds__(256) pproj_kernel(const float* __restrict__ x_proj_w){
  int e = blockIdx.y;
  int warp = threadIdx.x>>5, lane = threadIdx.x&31;
  int m = blockIdx.x*8 + warp;
  const float* row = g_xc + ((size_t)e*MM+m)*DIMC;
  float4 xv[4];
  #pragma unroll
  for(int i=0;i<4;i++) xv[i] = *(const float4*)(row + i*128 + lane*4);
  const float* wb = x_proj_w + (size_t)e*24*DIMC;
  #pragma unroll
  for(int c=0;c<24;c++){
    const float* wr = wb + (size_t)c*DIMC;
    float p=0.f;
    #pragma unroll
    for(int i=0;i<4;i++){
      float4 wv = *(const float4*)(wr + i*128 + lane*4);
      p = fmaf(xv[i].x,wv.x, fmaf(xv[i].y,wv.y, fmaf(xv[i].z,wv.z, fmaf(xv[i].w,wv.w, p))));
    }
    p = warp_sum(p);
    if(lane==0) g_P[((size_t)e*MM+m)*24 + c] = p;
  }
}

// ---------------- selective scan: 7-step ILP tiles (MUFU pipelined) ----------------
__global__ void __launch_bounds__(512) scan_kernel(const float* __restrict__ dt_proj_w,
                            const float* __restrict__ dt_proj_b,
                            const float* __restrict__ A_logs,
                            const float* __restrict__ Ds){
  int bx = blockIdx.x;
  int b = bx & 31;
  int k = (bx>>5)&3;
  int e = bx>>7;
  int d = threadIdx.x;
  __shared__ __align__(16) float sP[LL*8];
  __shared__ short sidx[LL];
  for(int t=threadIdx.x; t<LL; t+=blockDim.x){
    int tt = (k&1) ? (LL-1-t) : t;
    int idx = (k>=2) ? ((tt%HH)*WW + tt/HH) : tt;
    sidx[t] = (short)idx;
  }
  __syncthreads();
  for(int i=threadIdx.x;i<LL*6;i+=blockDim.x){
    int t=i/6, c=i-t*6;
    sP[t*8+c] = g_P[(((size_t)e*MM + b*LL + sidx[t])*24) + k*6 + c];
  }
  const float* dtw = dt_proj_w + (((size_t)(e*KK+k))*DIMC + d)*RR;
  float w0=dtw[0], w1=dtw[1], w2=dtw[2], w3=dtw[3];
  float dtb = dt_proj_b[(e*KK+k)*DIMC+d];
  float A  = -__expf(A_logs[e*(KK*DIMC) + k*DIMC + d]);
  float Dv = Ds[e*(KK*DIMC) + k*DIMC + d];
  __syncthreads();
  const float* xcb = g_xc + ((size_t)e*MM + b*LL)*DIMC + d;
  float* yb = g_y4 + (((size_t)(e*KK+k)*BDIM + b)*LL)*DIMC + d;
  float h = 0.f;
  // 28 tiles of 7: phase A (independent loads + MUFUs, ILP=7), phase B (FFMA chain)
  for(int t0=0; t0<LL; t0+=7){
    int   idxv[7];
    float xvv[7], dAv[7], duv[7], p5v[7];
    #pragma unroll
    for(int i=0;i<7;i++){
      idxv[i] = sidx[t0+i];
      xvv[i]  = xcb[(size_t)idxv[i]*DIMC];
    }
    #pragma unroll
    for(int i=0;i<7;i++){
      int t = t0+i;
      float4 pv = *(const float4*)(sP + t*8);
      float2 pw = *(const float2*)(sP + t*8 + 4);
      float s = fmaf(pv.x,w0, fmaf(pv.y,w1, fmaf(pv.z,w2, fmaf(pv.w,w3, dtb))));
      float dt = (s > 15.f) ? s : __logf(1.f + __expf(s));
      dAv[i] = __expf(dt*A);
      duv[i] = dt*xvv[i]*pw.x;
      p5v[i] = pw.y;
    }
    #pragma unroll
    for(int i=0;i<7;i++){
      h = fmaf(dAv[i], h, duv[i]);
      __stcs(yb + (size_t)idxv[i]*DIMC, fmaf(h, p5v[i], xvv[i]*Dv));
    }
  }
}

// ---------------- merge: single-pass (streaming y4 reads, one barrier) ----------------
__global__ void __launch_bounds__(512) merge_kernel(const float* __restrict__ norm_w,
                             const float* __restrict__ norm_b){
  int m = blockIdx.x;
  int d = threadIdx.x;
  int b = m / LL, l = m % LL;
  __shared__ float sh1[4][16], sh2[4][16];
  int wid = d>>5, lane = d&31;
  float v[4], z[4];
  #pragma unroll
  for(int e=0;e<4;e++){
    float a0 = __ldcs(&g_y4[ (((size_t)((e*KK+0)*BDIM + b))*LL + l)*DIMC + d ]);
    float a1 = __ldcs(&g_y4[ (((size_t)((e*KK+1)*BDIM + b))*LL + l)*DIMC + d ]);
    float a2 = __ldcs(&g_y4[ (((size_t)((e*KK+2)*BDIM + b))*LL + l)*DIMC + d ]);
    float a3 = __ldcs(&g_y4[ (((size_t)((e*KK+3)*BDIM + b))*LL + l)*DIMC + d ]);
    z[e] = g_xz[(size_t)m*NOUT + e*1024 + DIMC + d];
    v[e] = (a0+a1)+(a2+a3);
  }
  #pragma unroll
  for(int e=0;e<4;e++){
    float s1 = warp_sum(v[e]);
    float s2 = warp_sum(v[e]*v[e]);
    if(lane==0){ sh1[e][wid]=s1; sh2[e][wid]=s2; }
  }
  __syncthreads();
  float accd = 0.f;
  #pragma unroll
  for(int e=0;e<4;e++){
    float t1=0.f, t2=0.f;
    #pragma unroll
    for(int i=0;i<16;i++){ t1+=sh1[e][i]; t2+=sh2[e][i]; }
    float mu  = t1 * (1.f/DIMC);
    float var = t2 * (1.f/DIMC) - mu*mu;
    float nv = (v[e]-mu)*rsqrtf(var+1e-5f)*norm_w[e*DIMC+d] + norm_b[e*DIMC+d];
    float sz = z[e] / (1.f + __expf(-z[e]));
    accd = fmaf(nv*sz, g_comb[m*4+e], accd);
  }
  g_acc[(size_t)m*DIMC + d] = accd;
}

// ---------------- final mean over L (2 phases) ----------------
__global__ void out1_kernel(){
  int b = blockIdx.x, qq = blockIdx.y, d = threadIdx.x;
  float s = 0.f;
  #pragma unroll 7
  for(int l=qq*49; l<qq*49+49; l++) s += g_acc[((size_t)(b*LL+l))*DIMC + d];
  g_part[(b*4+qq)*DIMC + d] = s;
}
__global__ void out2_kernel(float* d_out){
  int b = blockIdx.x, d = threadIdx.x;
  float s = g_part[(b*4+0)*DIMC+d] + g_part[(b*4+1)*DIMC+d]
          + g_part[(b*4+2)*DIMC+d] + g_part[(b*4+3)*DIMC+d];
  d_out[b*DIMC + d] = s * (1.f/(float)LL);
}

extern "C" void kernel_launch(void* const* d_in, const int* in_sizes, int n_in,
                              void* d_out, int out_size){
  const float* x         = (const float*)d_in[0];
  const float* q         = (const float*)d_in[1];
  const float* temp      = (const float*)d_in[2];
  const float* in_proj_w = (const float*)d_in[3];
  const float* conv_w    = (const float*)d_in[4];
  const float* conv_b    = (const float*)d_in[5];
  const float* x_proj_w  = (const float*)d_in[6];
  const float* dt_proj_w = (const float*)d_in[7];
  const float* dt_proj_b = (const float*)d_in[8];
  const float* A_logs    = (const float*)d_in[9];
  const float* Ds        = (const float*)d_in[10];
  const float* norm_w    = (const float*)d_in[11];
  const float* norm_b    = (const float*)d_in[12];
  float* out = (float*)d_out;

  static cudaStream_t s2 = 0;
  static cudaEvent_t ev1 = 0, ev2 = 0;
  if(!s2){
    cudaStreamCreateWithFlags(&s2, cudaStreamNonBlocking);
    cudaEventCreateWithFlags(&ev1, cudaEventDisableTiming);
    cudaEventCreateWithFlags(&ev2, cudaEventDisableTiming);
  }

  const int GEMM_SMEM = 2*STAGE_B; // 81920
  cudaFuncSetAttribute(gemm_mma_kernel, cudaFuncAttributeMaxDynamicSharedMemorySize, GEMM_SMEM);

  size_t conv_units = (size_t)(MM + NOUT)*DIMC/8;
  convert_kernel<<<(int)((conv_units+255)/256), 256>>>(x, in_proj_w);

  // fork (R12/R15 schedule): s2 runs gating/aux + z-half GEMM concurrent with x-half GEMM
  cudaEventRecord(ev1, 0);
  cudaStreamWaitEvent(s2, ev1, 0);

  gemm_mma_kernel<<<dim3(16, MT), 256, GEMM_SMEM>>>(0);          // x-half (main)
  gating_kernel<<<784, 256, 0, s2>>>(x, q, temp);
  gr2_kernel<<<1, 256, 0, s2>>>(out, out_size);
  gemm_mma_kernel<<<dim3(16, MT), 256, GEMM_SMEM, s2>>>(1);      // z-half (s2, concurrent)
  cudaEventRecord(ev2, s2);

  conv2_kernel<<<dim3(BDIM, EE, 2), 512>>>(conv_w, conv_b);
  pproj_kernel<<<dim3(MM/8, EE), 256>>>(x_proj_w);
  scan_kernel<<<EE*KK*BDIM, 512>>>(dt_proj_w, dt_proj_b, A_logs, Ds);

  // join: z-half + gating results needed by merge
  cudaStreamWaitEvent(0, ev2, 0);
  merge_kernel<<<MM, 512>>>(norm_w, norm_b);
  out1_kernel<<<dim3(BDIM,4), 512>>>();
  out2_kernel<<<BDIM, 512>>>(out);
}